// round 1
// baseline (speedup 1.0000x reference)
#include <cuda_runtime.h>
#include <math.h>

// ---------------- problem dims (fixed) ----------------
#define Bc   2
#define LQ   1024
#define LKV  4096
#define Dm   512
#define NH   8
#define DHd  64
#define Ff   2048
#define MQ   (Bc*LQ)    // 2048
#define MKV  (Bc*LKV)   // 8192

// ---------------- scratch (device globals, no allocs) ----------------
__device__ float g_kv  [MKV*Dm];
__device__ float g_ln  [MQ*Dm];
__device__ float g_Q   [MQ*Dm];
__device__ float g_K   [MKV*Dm];
__device__ float g_V   [MKV*Dm];
__device__ float g_attn[MQ*Dm];
__device__ float g_x   [MQ*Dm];
__device__ float g_h1  [MQ*Ff];

// ---------------- elementwise kernels ----------------
__global__ void add2_k(const float* __restrict__ a, const float* __restrict__ b,
                       float* __restrict__ c, int n4) {
    int i = blockIdx.x * blockDim.x + threadIdx.x;
    if (i < n4) {
        float4 av = ((const float4*)a)[i];
        float4 bv = ((const float4*)b)[i];
        av.x += bv.x; av.y += bv.y; av.z += bv.z; av.w += bv.w;
        ((float4*)c)[i] = av;
    }
}

__global__ void copy_k(const float* __restrict__ a, float* __restrict__ c, int n4) {
    int i = blockIdx.x * blockDim.x + threadIdx.x;
    if (i < n4) ((float4*)c)[i] = ((const float4*)a)[i];
}

// ---------------- layernorm (+ optional pe add) ----------------
// one block per row, 128 threads, D=512 (4 floats per thread)
__global__ void ln_pe_k(const float* __restrict__ x, const float* __restrict__ g,
                        const float* __restrict__ b, const float* __restrict__ pe,
                        float* __restrict__ out) {
    __shared__ float red[8];
    const int row = blockIdx.x, tid = threadIdx.x;
    const float* xr = x + (size_t)row * Dm;
    float4 xv = *(const float4*)&xr[tid * 4];
    float sum = xv.x + xv.y + xv.z + xv.w;
    float sq  = xv.x*xv.x + xv.y*xv.y + xv.z*xv.z + xv.w*xv.w;
#pragma unroll
    for (int off = 16; off > 0; off >>= 1) {
        sum += __shfl_xor_sync(0xffffffffu, sum, off);
        sq  += __shfl_xor_sync(0xffffffffu, sq,  off);
    }
    if ((tid & 31) == 0) { red[tid >> 5] = sum; red[4 + (tid >> 5)] = sq; }
    __syncthreads();
    sum = red[0] + red[1] + red[2] + red[3];
    sq  = red[4] + red[5] + red[6] + red[7];
    float mu   = sum * (1.0f / Dm);
    float var  = sq * (1.0f / Dm) - mu * mu;
    float rstd = rsqrtf(var + 1e-6f);
    float4 gv = *(const float4*)&g[tid * 4];
    float4 bv = *(const float4*)&b[tid * 4];
    float4 r;
    r.x = (xv.x - mu) * rstd * gv.x + bv.x;
    r.y = (xv.y - mu) * rstd * gv.y + bv.y;
    r.z = (xv.z - mu) * rstd * gv.z + bv.z;
    r.w = (xv.w - mu) * rstd * gv.w + bv.w;
    if (pe) {
        const float4 pv = *(const float4*)&pe[(size_t)row * Dm + tid * 4];
        r.x += pv.x; r.y += pv.y; r.z += pv.z; r.w += pv.w;
    }
    *(float4*)&out[(size_t)row * Dm + tid * 4] = r;
}

// ---------------- fp32 tiled GEMM: C = op(A[M,K] @ W[K,N] + bias) (+res) ----------------
// 64x64 tile, BK=16, 256 threads, 4x4 per thread
template <bool RELU, bool RES>
__global__ void sgemm_k(const float* __restrict__ A, const float* __restrict__ W,
                        const float* __restrict__ bias, const float* __restrict__ res,
                        float* __restrict__ C, int M, int N, int K) {
    __shared__ float As[16][68];  // [k][m]
    __shared__ float Ws[16][68];  // [k][n]
    const int tid = threadIdx.x;
    const int tx = tid & 15, ty = tid >> 4;
    const int m0 = blockIdx.y * 64, n0 = blockIdx.x * 64;
    const int kl = tid & 15, mb = tid >> 4;  // A loader
    const int nl = tid & 63, kb = tid >> 6;  // W loader
    float acc[4][4] = {};

    for (int k0 = 0; k0 < K; k0 += 16) {
#pragma unroll
        for (int r = 0; r < 4; r++)
            As[kl][mb + r * 16] = A[(size_t)(m0 + mb + r * 16) * K + k0 + kl];
#pragma unroll
        for (int r = 0; r < 4; r++)
            Ws[kb + r * 4][nl] = W[(size_t)(k0 + kb + r * 4) * N + n0 + nl];
        __syncthreads();
#pragma unroll
        for (int k = 0; k < 16; k++) {
            float4 a4 = *(const float4*)&As[k][ty * 4];
            float4 b4 = *(const float4*)&Ws[k][tx * 4];
            float aa[4] = {a4.x, a4.y, a4.z, a4.w};
            float bb[4] = {b4.x, b4.y, b4.z, b4.w};
#pragma unroll
            for (int i = 0; i < 4; i++)
#pragma unroll
                for (int j = 0; j < 4; j++)
                    acc[i][j] += aa[i] * bb[j];
        }
        __syncthreads();
    }

#pragma unroll
    for (int i = 0; i < 4; i++) {
        size_t m = (size_t)(m0 + ty * 4 + i);
        int n = n0 + tx * 4;
        float4 bv = *(const float4*)&bias[n];
        float4 v  = make_float4(acc[i][0] + bv.x, acc[i][1] + bv.y,
                                acc[i][2] + bv.z, acc[i][3] + bv.w);
        if (RELU) {
            v.x = fmaxf(v.x, 0.f); v.y = fmaxf(v.y, 0.f);
            v.z = fmaxf(v.z, 0.f); v.w = fmaxf(v.w, 0.f);
        }
        if (RES) {
            float4 rv = *(const float4*)&res[m * N + n];
            v.x += rv.x; v.y += rv.y; v.z += rv.z; v.w += rv.w;
        }
        *(float4*)&C[m * N + n] = v;
    }
}

// ---------------- fused flash attention (fp32) ----------------
// block = 256 threads; tile = 64 q rows x dh64, loop over 64-row kv tiles
#define SPAD 68
#define ATTN_SMEM ((3 * 64 * SPAD + 128) * 4)

__global__ void attn64_k(const float* __restrict__ Qm, const float* __restrict__ Km,
                         const float* __restrict__ Vm, float* __restrict__ Om) {
    extern __shared__ float sm[];
    float* Qs  = sm;                 // [64][SPAD] q (pre-scaled)
    float* KP  = sm + 64 * SPAD;     // K^T [d][kv], later P [q][kv]
    float* Vs  = sm + 2 * 64 * SPAD; // [kv][d]
    float* m_s = sm + 3 * 64 * SPAD; // [64]
    float* l_s = m_s + 64;           // [64]

    const int tid = threadIdx.x;
    const int tx = tid & 15, ty = tid >> 4;
    const int b = blockIdx.z, h = blockIdx.y, qt = blockIdx.x;
    const size_t qrow0 = (size_t)b * LQ + qt * 64;
    const int hoff = h * DHd;

    for (int i = tid; i < 64 * 64; i += 256) {
        int r = i >> 6, d = i & 63;
        Qs[r * SPAD + d] = Qm[(qrow0 + r) * Dm + hoff + d] * 0.125f;  // 1/sqrt(64)
    }
    if (tid < 64) { m_s[tid] = -1e30f; l_s[tid] = 0.f; }
    float o[4][4] = {};
    __syncthreads();

    for (int t = 0; t < LKV / 64; t++) {
        size_t kv0 = (size_t)b * LKV + t * 64;
        for (int i = tid; i < 64 * 64; i += 256) {
            int r = i >> 6, d = i & 63;
            size_t gi = (kv0 + r) * Dm + hoff + d;
            KP[d * SPAD + r] = Km[gi];   // transposed
            Vs[r * SPAD + d] = Vm[gi];
        }
        __syncthreads();

        // S = Q K^T (4x4 per thread)
        float s[4][4] = {};
#pragma unroll
        for (int d = 0; d < 64; d += 4) {
            float qa[4][4], kbv[4][4];
#pragma unroll
            for (int i = 0; i < 4; i++) {
                float4 v = *(const float4*)&Qs[(ty * 4 + i) * SPAD + d];
                qa[i][0] = v.x; qa[i][1] = v.y; qa[i][2] = v.z; qa[i][3] = v.w;
            }
#pragma unroll
            for (int u = 0; u < 4; u++) {
                float4 v = *(const float4*)&KP[(d + u) * SPAD + tx * 4];
                kbv[u][0] = v.x; kbv[u][1] = v.y; kbv[u][2] = v.z; kbv[u][3] = v.w;
            }
#pragma unroll
            for (int i = 0; i < 4; i++)
#pragma unroll
                for (int u = 0; u < 4; u++)
#pragma unroll
                    for (int j = 0; j < 4; j++)
                        s[i][j] += qa[i][u] * kbv[u][j];
        }

        // online softmax update (rows live in one warp: lanes 0-15 / 16-31)
        float p[4][4], escale[4], mnew[4], lnew[4];
#pragma unroll
        for (int i = 0; i < 4; i++) {
            int ri = ty * 4 + i;
            float mx = fmaxf(fmaxf(s[i][0], s[i][1]), fmaxf(s[i][2], s[i][3]));
#pragma unroll
            for (int off = 8; off > 0; off >>= 1)
                mx = fmaxf(mx, __shfl_xor_sync(0xffffffffu, mx, off, 16));
            float mold = m_s[ri], lold = l_s[ri];
            float mn = fmaxf(mold, mx);
            float sum = 0.f;
#pragma unroll
            for (int j = 0; j < 4; j++) { p[i][j] = __expf(s[i][j] - mn); sum += p[i][j]; }
#pragma unroll
            for (int off = 8; off > 0; off >>= 1)
                sum += __shfl_xor_sync(0xffffffffu, sum, off, 16);
            float es = __expf(mold - mn);
            escale[i] = es; mnew[i] = mn; lnew[i] = lold * es + sum;
        }
        __syncwarp();
        if (tx == 0) {
#pragma unroll
            for (int i = 0; i < 4; i++) { m_s[ty * 4 + i] = mnew[i]; l_s[ty * 4 + i] = lnew[i]; }
        }
#pragma unroll
        for (int i = 0; i < 4; i++)
#pragma unroll
            for (int j = 0; j < 4; j++)
                o[i][j] *= escale[i];

        __syncthreads();  // everyone done reading K^T -> reuse KP for P
#pragma unroll
        for (int i = 0; i < 4; i++)
            *(float4*)&KP[(ty * 4 + i) * SPAD + tx * 4] =
                make_float4(p[i][0], p[i][1], p[i][2], p[i][3]);
        __syncthreads();

        // O += P V
#pragma unroll
        for (int kv = 0; kv < 64; kv += 4) {
            float pa[4][4], vb[4][4];
#pragma unroll
            for (int i = 0; i < 4; i++) {
                float4 v = *(const float4*)&KP[(ty * 4 + i) * SPAD + kv];
                pa[i][0] = v.x; pa[i][1] = v.y; pa[i][2] = v.z; pa[i][3] = v.w;
            }
#pragma unroll
            for (int u = 0; u < 4; u++) {
                float4 v = *(const float4*)&Vs[(kv + u) * SPAD + tx * 4];
                vb[u][0] = v.x; vb[u][1] = v.y; vb[u][2] = v.z; vb[u][3] = v.w;
            }
#pragma unroll
            for (int i = 0; i < 4; i++)
#pragma unroll
                for (int u = 0; u < 4; u++)
#pragma unroll
                    for (int j = 0; j < 4; j++)
                        o[i][j] += pa[i][u] * vb[u][j];
        }
        __syncthreads();  // before next tile overwrites KP/Vs
    }

#pragma unroll
    for (int i = 0; i < 4; i++) {
        int ri = ty * 4 + i;
        float inv = 1.f / l_s[ri];
        *(float4*)&Om[(qrow0 + ri) * Dm + hoff + tx * 4] =
            make_float4(o[i][0] * inv, o[i][1] * inv, o[i][2] * inv, o[i][3] * inv);
    }
}

// ---------------- host orchestration ----------------
extern "C" void kernel_launch(void* const* d_in, const int* in_sizes, int n_in,
                              void* d_out, int out_size) {
    const float* hs  = (const float*)d_in[0];
    const float* hpe = (const float*)d_in[1];
    const float* fs  = (const float*)d_in[2];
    const float* fpe = (const float*)d_in[3];
    const float* os_ = (const float*)d_in[4];
    const float* ope = (const float*)d_in[5];
    const float* f_Wq = (const float*)d_in[6],  *f_Wk = (const float*)d_in[7];
    const float* f_Wv = (const float*)d_in[8],  *f_Wo = (const float*)d_in[9];
    const float* f_bq = (const float*)d_in[10], *f_bk = (const float*)d_in[11];
    const float* f_bv = (const float*)d_in[12], *f_bo = (const float*)d_in[13];
    const float* f_g  = (const float*)d_in[14], *f_b  = (const float*)d_in[15];
    const float* o_Wq = (const float*)d_in[16], *o_Wk = (const float*)d_in[17];
    const float* o_Wv = (const float*)d_in[18], *o_Wo = (const float*)d_in[19];
    const float* o_bq = (const float*)d_in[20], *o_bk = (const float*)d_in[21];
    const float* o_bv = (const float*)d_in[22], *o_bo = (const float*)d_in[23];
    const float* o_g  = (const float*)d_in[24], *o_b  = (const float*)d_in[25];
    const float* W1 = (const float*)d_in[26], *b1 = (const float*)d_in[27];
    const float* W2 = (const float*)d_in[28], *b2 = (const float*)d_in[29];
    const float* n3g = (const float*)d_in[30], *n3b = (const float*)d_in[31];
    float* out = (float*)d_out;

    float *kv, *ln, *Qp, *Kp, *Vp, *at, *x, *h1;
    cudaGetSymbolAddress((void**)&kv, g_kv);
    cudaGetSymbolAddress((void**)&ln, g_ln);
    cudaGetSymbolAddress((void**)&Qp, g_Q);
    cudaGetSymbolAddress((void**)&Kp, g_K);
    cudaGetSymbolAddress((void**)&Vp, g_V);
    cudaGetSymbolAddress((void**)&at, g_attn);
    cudaGetSymbolAddress((void**)&x,  g_x);
    cudaGetSymbolAddress((void**)&h1, g_h1);

    cudaFuncSetAttribute(attn64_k, cudaFuncAttributeMaxDynamicSharedMemorySize, ATTN_SMEM);

    const int nq4  = MQ * Dm / 4;
    const int nkv4 = MKV * Dm / 4;
    dim3 g_qd(Dm / 64, MQ / 64);    // M=2048, N=512
    dim3 g_kvd(Dm / 64, MKV / 64);  // M=8192, N=512
    dim3 g_ffn1(Ff / 64, MQ / 64);  // N=2048
    dim3 g_attn(LQ / 64, NH, Bc);

    // passthrough outputs (independent, issue first)
    copy_k<<<nkv4 / 256, 256>>>(fs,  out + (size_t)MQ * Dm,                    nkv4);
    copy_k<<<nkv4 / 256, 256>>>(os_, out + (size_t)MQ * Dm + (size_t)MKV * Dm, nkv4);

    // x = hidden_states
    copy_k<<<nq4 / 256, 256>>>(hs, x, nq4);

    // ---- frame cross-attention sublayer ----
    add2_k<<<nkv4 / 256, 256>>>(fs, fpe, kv, nkv4);
    ln_pe_k<<<MQ, 128>>>(x, f_g, f_b, hpe, ln);
    sgemm_k<false, false><<<g_qd,  256>>>(ln, f_Wq, f_bq, nullptr, Qp, MQ,  Dm, Dm);
    sgemm_k<false, false><<<g_kvd, 256>>>(kv, f_Wk, f_bk, nullptr, Kp, MKV, Dm, Dm);
    sgemm_k<false, false><<<g_kvd, 256>>>(fs, f_Wv, f_bv, nullptr, Vp, MKV, Dm, Dm);
    attn64_k<<<g_attn, 256, ATTN_SMEM>>>(Qp, Kp, Vp, at);
    sgemm_k<false, true><<<g_qd, 256>>>(at, f_Wo, f_bo, x, x, MQ, Dm, Dm);

    // ---- object cross-attention sublayer ----
    add2_k<<<nkv4 / 256, 256>>>(os_, ope, kv, nkv4);
    ln_pe_k<<<MQ, 128>>>(x, o_g, o_b, hpe, ln);
    sgemm_k<false, false><<<g_qd,  256>>>(ln,  o_Wq, o_bq, nullptr, Qp, MQ,  Dm, Dm);
    sgemm_k<false, false><<<g_kvd, 256>>>(kv,  o_Wk, o_bk, nullptr, Kp, MKV, Dm, Dm);
    sgemm_k<false, false><<<g_kvd, 256>>>(os_, o_Wv, o_bv, nullptr, Vp, MKV, Dm, Dm);
    attn64_k<<<g_attn, 256, ATTN_SMEM>>>(Qp, Kp, Vp, at);
    sgemm_k<false, true><<<g_qd, 256>>>(at, o_Wo, o_bo, x, x, MQ, Dm, Dm);

    // ---- FFN sublayer ----
    ln_pe_k<<<MQ, 128>>>(x, n3g, n3b, nullptr, ln);
    sgemm_k<true,  false><<<g_ffn1, 256>>>(ln, W1, b1, nullptr, h1, MQ, Ff, Dm);
    sgemm_k<false, true><<<g_qd,   256>>>(h1, W2, b2, x, out, MQ, Dm, Ff);
}

// round 2
// speedup vs baseline: 1.7021x; 1.7021x over previous
#include <cuda_runtime.h>
#include <cstdint>

// ---------------- problem dims (fixed) ----------------
#define Bc   2
#define LQ   1024
#define LKV  4096
#define Dm   512
#define NH   8
#define DHd  64
#define Ff   2048
#define MQ   (Bc*LQ)    // 2048
#define MKV  (Bc*LKV)   // 8192

// ---------------- scratch ----------------
__device__ float g_kv  [MKV*Dm];
__device__ float g_ln  [MQ*Dm];
__device__ float g_Q   [MQ*Dm];
__device__ float g_K   [MKV*Dm];
__device__ float g_V   [MKV*Dm];
__device__ float g_attn[MQ*Dm];
__device__ float g_x   [MQ*Dm];
__device__ float g_h1  [MQ*Ff];

// ---------------- tf32 helpers ----------------
__device__ __forceinline__ uint32_t f2tf(float x) {
    uint32_t r;
    asm("cvt.rna.tf32.f32 %0, %1;" : "=r"(r) : "f"(x));
    return r;
}
__device__ __forceinline__ void mma_tf32(float c[4],
    uint32_t a0, uint32_t a1, uint32_t a2, uint32_t a3,
    uint32_t b0, uint32_t b1) {
    asm("mma.sync.aligned.m16n8k8.row.col.f32.tf32.tf32.f32 "
        "{%0,%1,%2,%3},{%4,%5,%6,%7},{%8,%9},{%0,%1,%2,%3};"
        : "+f"(c[0]), "+f"(c[1]), "+f"(c[2]), "+f"(c[3])
        : "r"(a0), "r"(a1), "r"(a2), "r"(a3), "r"(b0), "r"(b1));
}
__device__ __forceinline__ float ex2(float x) {
    float y;
    asm("ex2.approx.f32 %0, %1;" : "=f"(y) : "f"(x));
    return y;
}

// ---------------- elementwise ----------------
__global__ void add2_k(const float* __restrict__ a, const float* __restrict__ b,
                       float* __restrict__ c, int n4) {
    int i = blockIdx.x * blockDim.x + threadIdx.x;
    if (i < n4) {
        float4 av = ((const float4*)a)[i];
        float4 bv = ((const float4*)b)[i];
        av.x += bv.x; av.y += bv.y; av.z += bv.z; av.w += bv.w;
        ((float4*)c)[i] = av;
    }
}
__global__ void copy_k(const float* __restrict__ a, float* __restrict__ c, int n4) {
    int i = blockIdx.x * blockDim.x + threadIdx.x;
    if (i < n4) ((float4*)c)[i] = ((const float4*)a)[i];
}

// ---------------- layernorm (+ optional pe add) ----------------
__global__ void ln_pe_k(const float* __restrict__ x, const float* __restrict__ g,
                        const float* __restrict__ b, const float* __restrict__ pe,
                        float* __restrict__ out) {
    __shared__ float red[8];
    const int row = blockIdx.x, tid = threadIdx.x;
    const float* xr = x + (size_t)row * Dm;
    float4 xv = *(const float4*)&xr[tid * 4];
    float sum = xv.x + xv.y + xv.z + xv.w;
    float sq  = xv.x*xv.x + xv.y*xv.y + xv.z*xv.z + xv.w*xv.w;
#pragma unroll
    for (int off = 16; off > 0; off >>= 1) {
        sum += __shfl_xor_sync(0xffffffffu, sum, off);
        sq  += __shfl_xor_sync(0xffffffffu, sq,  off);
    }
    if ((tid & 31) == 0) { red[tid >> 5] = sum; red[4 + (tid >> 5)] = sq; }
    __syncthreads();
    sum = red[0] + red[1] + red[2] + red[3];
    sq  = red[4] + red[5] + red[6] + red[7];
    float mu   = sum * (1.0f / Dm);
    float var  = sq * (1.0f / Dm) - mu * mu;
    float rstd = rsqrtf(var + 1e-6f);
    float4 gv = *(const float4*)&g[tid * 4];
    float4 bv = *(const float4*)&b[tid * 4];
    float4 r;
    r.x = (xv.x - mu) * rstd * gv.x + bv.x;
    r.y = (xv.y - mu) * rstd * gv.y + bv.y;
    r.z = (xv.z - mu) * rstd * gv.z + bv.z;
    r.w = (xv.w - mu) * rstd * gv.w + bv.w;
    if (pe) {
        const float4 pv = *(const float4*)&pe[(size_t)row * Dm + tid * 4];
        r.x += pv.x; r.y += pv.y; r.z += pv.z; r.w += pv.w;
    }
    *(float4*)&out[(size_t)row * Dm + tid * 4] = r;
}

// ---------------- tf32 tensor-core GEMM ----------------
// C[M,N] = A[M,K] @ W[K,N] + bias (opt relu, opt +res)
// BM=128 BN=64 BK=32, 256 threads = 8 warps (4m x 2n), warp tile 32x32.
// smem holds operands pre-permuted into mma fragment order.
template <bool RELU, bool RES>
__global__ void __launch_bounds__(256) tgemm_k(
    const float* __restrict__ A, const float* __restrict__ W,
    const float* __restrict__ bias, const float* __restrict__ res,
    float* __restrict__ C, int M, int N, int K)
{
    __shared__ uint32_t As[128 * 32];  // [mi*4+ks][lane*4+reg]
    __shared__ uint32_t Bs[32 * 64];   // [ni*4+ks][lane*2+reg]
    const int tid = threadIdx.x;
    const int lane = tid & 31, w = tid >> 5;
    const int wm = w >> 1, wn = w & 1;
    const int m0 = blockIdx.y * 128, n0 = blockIdx.x * 64;
    float acc[2][4][4] = {};

    for (int k0 = 0; k0 < K; k0 += 32) {
        // fill A (permuted to A-fragment order)
#pragma unroll
        for (int it = 0; it < 4; it++) {
            int f = it * 256 + tid;
            int ml = f >> 3, k4 = f & 7;
            float4 v = *(const float4*)&A[(size_t)(m0 + ml) * K + k0 + k4 * 4];
            float vv[4] = {v.x, v.y, v.z, v.w};
            int mi = ml >> 4, r = ml & 15;
#pragma unroll
            for (int e = 0; e < 4; e++) {
                int kl = k4 * 4 + e;
                int ks = kl >> 3, c = kl & 7;
                As[((mi * 4 + ks) << 7) + (((r & 7) * 4 + (c & 3)) << 2)
                   + ((r >> 3) + ((c >> 2) << 1))] = f2tf(vv[e]);
            }
        }
        // fill B (permuted to B-fragment order)
#pragma unroll
        for (int it = 0; it < 2; it++) {
            int f = it * 256 + tid;
            int kl = f >> 4, n4 = f & 15;
            float4 v = *(const float4*)&W[(size_t)(k0 + kl) * N + n0 + n4 * 4];
            float vv[4] = {v.x, v.y, v.z, v.w};
            int ks = kl >> 3, kk = kl & 7;
#pragma unroll
            for (int e = 0; e < 4; e++) {
                int nl = n4 * 4 + e;
                int ni = nl >> 3, nn = nl & 7;
                Bs[((ni * 4 + ks) << 6) + ((nn * 4 + (kk & 3)) << 1) + (kk >> 2)]
                    = f2tf(vv[e]);
            }
        }
        __syncthreads();
#pragma unroll
        for (int ks = 0; ks < 4; ks++) {
            uint32_t a[2][4], b[4][2];
#pragma unroll
            for (int i = 0; i < 2; i++) {
                int mi = wm * 2 + i;
                uint4 t = *(const uint4*)&As[((mi * 4 + ks) << 7) + (lane << 2)];
                a[i][0] = t.x; a[i][1] = t.y; a[i][2] = t.z; a[i][3] = t.w;
            }
#pragma unroll
            for (int j = 0; j < 4; j++) {
                int ni = wn * 4 + j;
                uint2 t = *(const uint2*)&Bs[((ni * 4 + ks) << 6) + (lane << 1)];
                b[j][0] = t.x; b[j][1] = t.y;
            }
#pragma unroll
            for (int i = 0; i < 2; i++)
#pragma unroll
                for (int j = 0; j < 4; j++)
                    mma_tf32(acc[i][j], a[i][0], a[i][1], a[i][2], a[i][3],
                             b[j][0], b[j][1]);
        }
        __syncthreads();
    }

    // epilogue: acc layout c0,c1 = row g; c2,c3 = row g+8; cols 2*(lane%4)+{0,1}
#pragma unroll
    for (int i = 0; i < 2; i++) {
        int mrow0 = m0 + wm * 32 + i * 16 + (lane >> 2);
#pragma unroll
        for (int j = 0; j < 4; j++) {
            int ncol = n0 + wn * 32 + j * 8 + 2 * (lane & 3);
            float2 bv = *(const float2*)&bias[ncol];
#pragma unroll
            for (int hh = 0; hh < 2; hh++) {
                size_t m = (size_t)(mrow0 + hh * 8);
                float2 v = make_float2(acc[i][j][hh * 2 + 0] + bv.x,
                                       acc[i][j][hh * 2 + 1] + bv.y);
                if (RELU) { v.x = fmaxf(v.x, 0.f); v.y = fmaxf(v.y, 0.f); }
                if (RES) {
                    float2 rv = *(const float2*)&res[m * N + ncol];
                    v.x += rv.x; v.y += rv.y;
                }
                *(float2*)&C[m * N + ncol] = v;
            }
        }
    }
}

// ---------------- tf32 flash attention ----------------
// block = 128 threads (4 warps), q tile 64, kv tile 64, dh = 64.
// Each warp owns a 16-row q strip over full 64 kv columns.
#define QPAD 68
#define VPAD 72
#define ATTN_SMEM ((64 * (3 * QPAD + VPAD)) * 4)

__global__ void __launch_bounds__(128) fattn_k(
    const float* __restrict__ Qm, const float* __restrict__ Km,
    const float* __restrict__ Vm, float* __restrict__ Om)
{
    extern __shared__ uint32_t sm[];
    uint32_t* Qs = sm;                 // [64][QPAD]  (A operand: q x dh)
    uint32_t* Ks = Qs + 64 * QPAD;     // [64][QPAD]  (B operand: kv x dh)
    uint32_t* Ps = Ks + 64 * QPAD;     // [64][QPAD]  (A operand: q x kv)
    uint32_t* Vs = Ps + 64 * QPAD;     // [64][VPAD]  (B operand: kv x dh)

    const int tid = threadIdx.x;
    const int lane = tid & 31, w = tid >> 5;
    const int g = lane >> 2, qd = lane & 3;
    const int bb = blockIdx.z, hh = blockIdx.y, qt = blockIdx.x;
    const size_t qrow0 = (size_t)bb * LQ + qt * 64;
    const int hoff = hh * DHd;
    const int mb = w * 16;

    const float qscale = 0.125f * 1.4426950408889634f;  // 1/sqrt(dh) * log2(e)
#pragma unroll
    for (int it = 0; it < 8; it++) {
        int f = it * 128 + tid;        // 64 rows x 16 float4
        int r = f >> 4, c4 = f & 15;
        float4 v = *(const float4*)&Qm[(qrow0 + r) * Dm + hoff + c4 * 4];
        uint32_t* dst = &Qs[r * QPAD + c4 * 4];
        dst[0] = f2tf(v.x * qscale); dst[1] = f2tf(v.y * qscale);
        dst[2] = f2tf(v.z * qscale); dst[3] = f2tf(v.w * qscale);
    }

    float o[8][4] = {};
    float mrow[2] = {-1e30f, -1e30f};
    float lrow[2] = {0.f, 0.f};

    for (int t = 0; t < LKV / 64; t++) {
        __syncthreads();   // previous tile's PV reads done
        size_t kv0 = (size_t)bb * LKV + t * 64;
#pragma unroll
        for (int it = 0; it < 8; it++) {
            int f = it * 128 + tid;
            int r = f >> 4, c4 = f & 15;
            size_t gi = (kv0 + r) * Dm + hoff + c4 * 4;
            float4 kv_ = *(const float4*)&Km[gi];
            uint32_t* kd = &Ks[r * QPAD + c4 * 4];
            kd[0] = f2tf(kv_.x); kd[1] = f2tf(kv_.y);
            kd[2] = f2tf(kv_.z); kd[3] = f2tf(kv_.w);
            float4 vv = *(const float4*)&Vm[gi];
            uint32_t* vd = &Vs[r * VPAD + c4 * 4];
            vd[0] = f2tf(vv.x); vd[1] = f2tf(vv.y);
            vd[2] = f2tf(vv.z); vd[3] = f2tf(vv.w);
        }
        __syncthreads();

        // ---- S = Q @ K^T  (accum layout m16n8) ----
        float s[8][4] = {};
#pragma unroll
        for (int ks = 0; ks < 8; ks++) {
            uint32_t a0 = Qs[(mb + g) * QPAD + ks * 8 + qd];
            uint32_t a1 = Qs[(mb + g + 8) * QPAD + ks * 8 + qd];
            uint32_t a2 = Qs[(mb + g) * QPAD + ks * 8 + qd + 4];
            uint32_t a3 = Qs[(mb + g + 8) * QPAD + ks * 8 + qd + 4];
#pragma unroll
            for (int ni = 0; ni < 8; ni++) {
                uint32_t b0 = Ks[(ni * 8 + g) * QPAD + ks * 8 + qd];
                uint32_t b1 = Ks[(ni * 8 + g) * QPAD + ks * 8 + qd + 4];
                mma_tf32(s[ni], a0, a1, a2, a3, b0, b1);
            }
        }

        // ---- online softmax (rows g and g+8, reduce over lane quad) ----
        float mx0 = -1e30f, mx1 = -1e30f;
#pragma unroll
        for (int ni = 0; ni < 8; ni++) {
            mx0 = fmaxf(mx0, fmaxf(s[ni][0], s[ni][1]));
            mx1 = fmaxf(mx1, fmaxf(s[ni][2], s[ni][3]));
        }
        mx0 = fmaxf(mx0, __shfl_xor_sync(~0u, mx0, 1));
        mx0 = fmaxf(mx0, __shfl_xor_sync(~0u, mx0, 2));
        mx1 = fmaxf(mx1, __shfl_xor_sync(~0u, mx1, 1));
        mx1 = fmaxf(mx1, __shfl_xor_sync(~0u, mx1, 2));
        float mn0 = fmaxf(mrow[0], mx0), mn1 = fmaxf(mrow[1], mx1);
        float sum0 = 0.f, sum1 = 0.f;
#pragma unroll
        for (int ni = 0; ni < 8; ni++) {
            s[ni][0] = ex2(s[ni][0] - mn0); s[ni][1] = ex2(s[ni][1] - mn0);
            s[ni][2] = ex2(s[ni][2] - mn1); s[ni][3] = ex2(s[ni][3] - mn1);
            sum0 += s[ni][0] + s[ni][1];
            sum1 += s[ni][2] + s[ni][3];
        }
        sum0 += __shfl_xor_sync(~0u, sum0, 1); sum0 += __shfl_xor_sync(~0u, sum0, 2);
        sum1 += __shfl_xor_sync(~0u, sum1, 1); sum1 += __shfl_xor_sync(~0u, sum1, 2);
        float es0 = ex2(mrow[0] - mn0), es1 = ex2(mrow[1] - mn1);
        mrow[0] = mn0; mrow[1] = mn1;
        lrow[0] = lrow[0] * es0 + sum0;
        lrow[1] = lrow[1] * es1 + sum1;
#pragma unroll
        for (int ni = 0; ni < 8; ni++) {
            o[ni][0] *= es0; o[ni][1] *= es0;
            o[ni][2] *= es1; o[ni][3] *= es1;
        }

        // ---- store P into smem (A-operand layout for PV) ----
#pragma unroll
        for (int ni = 0; ni < 8; ni++) {
            Ps[(mb + g) * QPAD + ni * 8 + 2 * qd]         = f2tf(s[ni][0]);
            Ps[(mb + g) * QPAD + ni * 8 + 2 * qd + 1]     = f2tf(s[ni][1]);
            Ps[(mb + g + 8) * QPAD + ni * 8 + 2 * qd]     = f2tf(s[ni][2]);
            Ps[(mb + g + 8) * QPAD + ni * 8 + 2 * qd + 1] = f2tf(s[ni][3]);
        }
        __syncwarp();

        // ---- O += P @ V ----
#pragma unroll
        for (int ks = 0; ks < 8; ks++) {
            uint32_t a0 = Ps[(mb + g) * QPAD + ks * 8 + qd];
            uint32_t a1 = Ps[(mb + g + 8) * QPAD + ks * 8 + qd];
            uint32_t a2 = Ps[(mb + g) * QPAD + ks * 8 + qd + 4];
            uint32_t a3 = Ps[(mb + g + 8) * QPAD + ks * 8 + qd + 4];
#pragma unroll
            for (int ni = 0; ni < 8; ni++) {
                uint32_t b0 = Vs[(ks * 8 + qd) * VPAD + ni * 8 + g];
                uint32_t b1 = Vs[(ks * 8 + qd + 4) * VPAD + ni * 8 + g];
                mma_tf32(o[ni], a0, a1, a2, a3, b0, b1);
            }
        }
    }

    float inv0 = 1.f / lrow[0], inv1 = 1.f / lrow[1];
#pragma unroll
    for (int ni = 0; ni < 8; ni++) {
        int ncol = hoff + ni * 8 + 2 * qd;
        *(float2*)&Om[(qrow0 + mb + g) * Dm + ncol] =
            make_float2(o[ni][0] * inv0, o[ni][1] * inv0);
        *(float2*)&Om[(qrow0 + mb + g + 8) * Dm + ncol] =
            make_float2(o[ni][2] * inv1, o[ni][3] * inv1);
    }
}

// ---------------- host orchestration ----------------
extern "C" void kernel_launch(void* const* d_in, const int* in_sizes, int n_in,
                              void* d_out, int out_size) {
    const float* hs  = (const float*)d_in[0];
    const float* hpe = (const float*)d_in[1];
    const float* fs  = (const float*)d_in[2];
    const float* fpe = (const float*)d_in[3];
    const float* os_ = (const float*)d_in[4];
    const float* ope = (const float*)d_in[5];
    const float* f_Wq = (const float*)d_in[6],  *f_Wk = (const float*)d_in[7];
    const float* f_Wv = (const float*)d_in[8],  *f_Wo = (const float*)d_in[9];
    const float* f_bq = (const float*)d_in[10], *f_bk = (const float*)d_in[11];
    const float* f_bv = (const float*)d_in[12], *f_bo = (const float*)d_in[13];
    const float* f_g  = (const float*)d_in[14], *f_b  = (const float*)d_in[15];
    const float* o_Wq = (const float*)d_in[16], *o_Wk = (const float*)d_in[17];
    const float* o_Wv = (const float*)d_in[18], *o_Wo = (const float*)d_in[19];
    const float* o_bq = (const float*)d_in[20], *o_bk = (const float*)d_in[21];
    const float* o_bv = (const float*)d_in[22], *o_bo = (const float*)d_in[23];
    const float* o_g  = (const float*)d_in[24], *o_b  = (const float*)d_in[25];
    const float* W1 = (const float*)d_in[26], *b1 = (const float*)d_in[27];
    const float* W2 = (const float*)d_in[28], *b2 = (const float*)d_in[29];
    const float* n3g = (const float*)d_in[30], *n3b = (const float*)d_in[31];
    float* out = (float*)d_out;

    float *kv, *ln, *Qp, *Kp, *Vp, *at, *x, *h1;
    cudaGetSymbolAddress((void**)&kv, g_kv);
    cudaGetSymbolAddress((void**)&ln, g_ln);
    cudaGetSymbolAddress((void**)&Qp, g_Q);
    cudaGetSymbolAddress((void**)&Kp, g_K);
    cudaGetSymbolAddress((void**)&Vp, g_V);
    cudaGetSymbolAddress((void**)&at, g_attn);
    cudaGetSymbolAddress((void**)&x,  g_x);
    cudaGetSymbolAddress((void**)&h1, g_h1);

    cudaFuncSetAttribute(fattn_k, cudaFuncAttributeMaxDynamicSharedMemorySize, ATTN_SMEM);

    const int nq4  = MQ * Dm / 4;
    const int nkv4 = MKV * Dm / 4;
    dim3 g_qd(Dm / 64, MQ / 128);      // (8,16)
    dim3 g_kvd(Dm / 64, MKV / 128);    // (8,64)
    dim3 g_ffn1(Ff / 64, MQ / 128);    // (32,16)
    dim3 g_attn(LQ / 64, NH, Bc);      // (16,8,2)

    // passthrough outputs
    copy_k<<<nkv4 / 256, 256>>>(fs,  out + (size_t)MQ * Dm,                    nkv4);
    copy_k<<<nkv4 / 256, 256>>>(os_, out + (size_t)MQ * Dm + (size_t)MKV * Dm, nkv4);

    copy_k<<<nq4 / 256, 256>>>(hs, x, nq4);

    // ---- frame cross-attention sublayer ----
    add2_k<<<nkv4 / 256, 256>>>(fs, fpe, kv, nkv4);
    ln_pe_k<<<MQ, 128>>>(x, f_g, f_b, hpe, ln);
    tgemm_k<false, false><<<g_qd,  256>>>(ln, f_Wq, f_bq, nullptr, Qp, MQ,  Dm, Dm);
    tgemm_k<false, false><<<g_kvd, 256>>>(kv, f_Wk, f_bk, nullptr, Kp, MKV, Dm, Dm);
    tgemm_k<false, false><<<g_kvd, 256>>>(fs, f_Wv, f_bv, nullptr, Vp, MKV, Dm, Dm);
    fattn_k<<<g_attn, 128, ATTN_SMEM>>>(Qp, Kp, Vp, at);
    tgemm_k<false, true><<<g_qd, 256>>>(at, f_Wo, f_bo, x, x, MQ, Dm, Dm);

    // ---- object cross-attention sublayer ----
    add2_k<<<nkv4 / 256, 256>>>(os_, ope, kv, nkv4);
    ln_pe_k<<<MQ, 128>>>(x, o_g, o_b, hpe, ln);
    tgemm_k<false, false><<<g_qd,  256>>>(ln,  o_Wq, o_bq, nullptr, Qp, MQ,  Dm, Dm);
    tgemm_k<false, false><<<g_kvd, 256>>>(kv,  o_Wk, o_bk, nullptr, Kp, MKV, Dm, Dm);
    tgemm_k<false, false><<<g_kvd, 256>>>(os_, o_Wv, o_bv, nullptr, Vp, MKV, Dm, Dm);
    fattn_k<<<g_attn, 128, ATTN_SMEM>>>(Qp, Kp, Vp, at);
    tgemm_k<false, true><<<g_qd, 256>>>(at, o_Wo, o_bo, x, x, MQ, Dm, Dm);

    // ---- FFN sublayer ----
    ln_pe_k<<<MQ, 128>>>(x, n3g, n3b, nullptr, ln);
    tgemm_k<true,  false><<<g_ffn1, 256>>>(ln, W1, b1, nullptr, h1, MQ, Ff, Dm);
    tgemm_k<false, true><<<g_qd,   256>>>(h1, W2, b2, x, out, MQ, Dm, Ff);
}

// round 3
// speedup vs baseline: 2.3811x; 1.3989x over previous
#include <cuda_runtime.h>
#include <cstdint>

// ---------------- problem dims (fixed) ----------------
#define Bc   2
#define LQ   1024
#define LKV  4096
#define Dm   512
#define NH   8
#define DHd  64
#define Ff   2048
#define MQ   (Bc*LQ)    // 2048
#define MKV  (Bc*LKV)   // 8192

// ---------------- scratch ----------------
__device__ float g_ln  [MQ*Dm];
__device__ float g_Q   [MQ*Dm];
__device__ float g_K   [MKV*Dm];
__device__ float g_V   [MKV*Dm];
__device__ float g_attn[MQ*Dm];
__device__ float g_x   [MQ*Dm];
__device__ float g_h1  [MQ*Ff];

// ---------------- tf32 helpers ----------------
__device__ __forceinline__ uint32_t f2tf(float x) {
    uint32_t r;
    asm("cvt.rna.tf32.f32 %0, %1;" : "=r"(r) : "f"(x));
    return r;
}
__device__ __forceinline__ void mma_tf32(float c[4],
    uint32_t a0, uint32_t a1, uint32_t a2, uint32_t a3,
    uint32_t b0, uint32_t b1) {
    asm("mma.sync.aligned.m16n8k8.row.col.f32.tf32.tf32.f32 "
        "{%0,%1,%2,%3},{%4,%5,%6,%7},{%8,%9},{%0,%1,%2,%3};"
        : "+f"(c[0]), "+f"(c[1]), "+f"(c[2]), "+f"(c[3])
        : "r"(a0), "r"(a1), "r"(a2), "r"(a3), "r"(b0), "r"(b1));
}
__device__ __forceinline__ float ex2(float x) {
    float y;
    asm("ex2.approx.f32 %0, %1;" : "=f"(y) : "f"(x));
    return y;
}

// ---------------- elementwise ----------------
__global__ void copy_k(const float* __restrict__ a, float* __restrict__ c, int n4) {
    int i = blockIdx.x * blockDim.x + threadIdx.x;
    if (i < n4) ((float4*)c)[i] = ((const float4*)a)[i];
}

// ---------------- layernorm (+ optional pe add) ----------------
__global__ void ln_pe_k(const float* __restrict__ x, const float* __restrict__ g,
                        const float* __restrict__ b, const float* __restrict__ pe,
                        float* __restrict__ out) {
    __shared__ float red[8];
    const int row = blockIdx.x, tid = threadIdx.x;
    const float* xr = x + (size_t)row * Dm;
    float4 xv = *(const float4*)&xr[tid * 4];
    float sum = xv.x + xv.y + xv.z + xv.w;
    float sq  = xv.x*xv.x + xv.y*xv.y + xv.z*xv.z + xv.w*xv.w;
#pragma unroll
    for (int off = 16; off > 0; off >>= 1) {
        sum += __shfl_xor_sync(0xffffffffu, sum, off);
        sq  += __shfl_xor_sync(0xffffffffu, sq,  off);
    }
    if ((tid & 31) == 0) { red[tid >> 5] = sum; red[4 + (tid >> 5)] = sq; }
    __syncthreads();
    sum = red[0] + red[1] + red[2] + red[3];
    sq  = red[4] + red[5] + red[6] + red[7];
    float mu   = sum * (1.0f / Dm);
    float var  = sq * (1.0f / Dm) - mu * mu;
    float rstd = rsqrtf(var + 1e-6f);
    float4 gv = *(const float4*)&g[tid * 4];
    float4 bv = *(const float4*)&b[tid * 4];
    float4 r;
    r.x = (xv.x - mu) * rstd * gv.x + bv.x;
    r.y = (xv.y - mu) * rstd * gv.y + bv.y;
    r.z = (xv.z - mu) * rstd * gv.z + bv.z;
    r.w = (xv.w - mu) * rstd * gv.w + bv.w;
    if (pe) {
        const float4 pv = *(const float4*)&pe[(size_t)row * Dm + tid * 4];
        r.x += pv.x; r.y += pv.y; r.z += pv.z; r.w += pv.w;
    }
    *(float4*)&out[(size_t)row * Dm + tid * 4] = r;
}

// ---------------- tf32 tensor-core GEMM, pipelined ----------------
// C[M,N] = op((A [+A2]) @ W + bias) [+res]
// BM=128 BN=128 BK=32, 256 threads = 8 warps (2m x 4n), warp tile 64x32.
// Plain row-major smem: A pitch 36 (bank=4g+qd bijective), B pitch 136 (8qd+g).
// Double buffered, 1 syncthreads per k-slice, register prefetch.
#define GEMM_SMEM ((2*128*36 + 2*32*136) * 4)

template <bool ADD2, bool RELU, bool RES>
__global__ void __launch_bounds__(256, 1) tgemm_k(
    const float* __restrict__ A, const float* __restrict__ A2,
    const float* __restrict__ W, const float* __restrict__ bias,
    const float* __restrict__ res, float* __restrict__ C,
    int M, int N, int K)
{
    extern __shared__ uint32_t smg[];
    uint32_t* As = smg;                // [2][128*36]
    uint32_t* Bs = smg + 2 * 128 * 36; // [2][32*136]
    const int tid = threadIdx.x;
    const int lane = tid & 31, w = tid >> 5;
    const int wm = w >> 2, wn = w & 3;
    const int g = lane >> 2, qd = lane & 3;
    const int m0 = blockIdx.y * 128, n0 = blockIdx.x * 128;
    const int ar = tid >> 3, ac4 = (tid & 7) * 4;   // A fill: row-in-32, col
    const int br = tid >> 5, bc4 = (tid & 31) * 4;  // B fill: row-in-8,  col

    float4 la[4], lb[4];
    float acc[4][4][4];
#pragma unroll
    for (int i = 0; i < 4; i++)
#pragma unroll
        for (int j = 0; j < 4; j++)
#pragma unroll
            for (int e = 0; e < 4; e++) acc[i][j][e] = 0.f;

    // prefetch slice 0
#pragma unroll
    for (int it = 0; it < 4; it++) {
        la[it] = *(const float4*)&A[(size_t)(m0 + it * 32 + ar) * K + ac4];
        if (ADD2) {
            float4 t = *(const float4*)&A2[(size_t)(m0 + it * 32 + ar) * K + ac4];
            la[it].x += t.x; la[it].y += t.y; la[it].z += t.z; la[it].w += t.w;
        }
    }
#pragma unroll
    for (int it = 0; it < 4; it++)
        lb[it] = *(const float4*)&W[(size_t)(it * 8 + br) * N + n0 + bc4];

    const int KT = K >> 5;
    for (int kt = 0; kt < KT; kt++) {
        uint32_t* as = As + (kt & 1) * (128 * 36);
        uint32_t* bs = Bs + (kt & 1) * (32 * 136);
#pragma unroll
        for (int it = 0; it < 4; it++) {
            uint4 v = { f2tf(la[it].x), f2tf(la[it].y), f2tf(la[it].z), f2tf(la[it].w) };
            *(uint4*)&as[(it * 32 + ar) * 36 + ac4] = v;
        }
#pragma unroll
        for (int it = 0; it < 4; it++) {
            uint4 v = { f2tf(lb[it].x), f2tf(lb[it].y), f2tf(lb[it].z), f2tf(lb[it].w) };
            *(uint4*)&bs[(it * 8 + br) * 136 + bc4] = v;
        }
        __syncthreads();
        if (kt + 1 < KT) {
            const int k1 = (kt + 1) << 5;
#pragma unroll
            for (int it = 0; it < 4; it++) {
                la[it] = *(const float4*)&A[(size_t)(m0 + it * 32 + ar) * K + k1 + ac4];
                if (ADD2) {
                    float4 t = *(const float4*)&A2[(size_t)(m0 + it * 32 + ar) * K + k1 + ac4];
                    la[it].x += t.x; la[it].y += t.y; la[it].z += t.z; la[it].w += t.w;
                }
            }
#pragma unroll
            for (int it = 0; it < 4; it++)
                lb[it] = *(const float4*)&W[(size_t)(k1 + it * 8 + br) * N + n0 + bc4];
        }
#pragma unroll
        for (int ks = 0; ks < 4; ks++) {
            uint32_t af[4][4], bf[4][2];
#pragma unroll
            for (int mi = 0; mi < 4; mi++) {
                const uint32_t* p = &as[(wm * 64 + mi * 16 + g) * 36 + ks * 8 + qd];
                af[mi][0] = p[0]; af[mi][1] = p[8 * 36];
                af[mi][2] = p[4]; af[mi][3] = p[8 * 36 + 4];
            }
#pragma unroll
            for (int ni = 0; ni < 4; ni++) {
                const uint32_t* p = &bs[(ks * 8 + qd) * 136 + wn * 32 + ni * 8 + g];
                bf[ni][0] = p[0]; bf[ni][1] = p[4 * 136];
            }
#pragma unroll
            for (int mi = 0; mi < 4; mi++)
#pragma unroll
                for (int ni = 0; ni < 4; ni++)
                    mma_tf32(acc[mi][ni], af[mi][0], af[mi][1], af[mi][2], af[mi][3],
                             bf[ni][0], bf[ni][1]);
        }
    }

#pragma unroll
    for (int mi = 0; mi < 4; mi++) {
        int mrow = m0 + wm * 64 + mi * 16 + g;
#pragma unroll
        for (int ni = 0; ni < 4; ni++) {
            int ncol = n0 + wn * 32 + ni * 8 + 2 * qd;
            float2 bv = *(const float2*)&bias[ncol];
#pragma unroll
            for (int hh = 0; hh < 2; hh++) {
                size_t m = (size_t)(mrow + hh * 8);
                float2 v = make_float2(acc[mi][ni][hh * 2 + 0] + bv.x,
                                       acc[mi][ni][hh * 2 + 1] + bv.y);
                if (RELU) { v.x = fmaxf(v.x, 0.f); v.y = fmaxf(v.y, 0.f); }
                if (RES) {
                    float2 rv = *(const float2*)&res[m * N + ncol];
                    v.x += rv.x; v.y += rv.y;
                }
                *(float2*)&C[m * N + ncol] = v;
            }
        }
    }
}

// ---------------- tf32 flash attention ----------------
// 64 threads = 2 warps; q tile 64 (32 rows per warp), kv tile 64, dh 64.
// P overlays the K smem region (synced) to save smem.
#define QPAD 68
#define VPAD 72
#define ATTN_SMEM ((2 * 64 * QPAD + 64 * VPAD) * 4)

__global__ void __launch_bounds__(64) fattn_k(
    const float* __restrict__ Qm, const float* __restrict__ Km,
    const float* __restrict__ Vm, float* __restrict__ Om)
{
    extern __shared__ uint32_t sm[];
    uint32_t* Qs = sm;                 // [64][QPAD] q (pre-scaled)
    uint32_t* KP = sm + 64 * QPAD;     // K tile, later P tile
    uint32_t* Vs = sm + 2 * 64 * QPAD; // [64][VPAD]

    const int tid = threadIdx.x;
    const int lane = tid & 31, w = tid >> 5;
    const int g = lane >> 2, qd = lane & 3;
    const int bb = blockIdx.z, hh = blockIdx.y, qt = blockIdx.x;
    const size_t qrow0 = (size_t)bb * LQ + qt * 64;
    const int hoff = hh * DHd;
    const int mb = w * 32;

    const float qscale = 0.125f * 1.4426950408889634f;
#pragma unroll
    for (int it = 0; it < 16; it++) {
        int f = it * 64 + tid;
        int r = f >> 4, c4 = f & 15;
        float4 v = *(const float4*)&Qm[(qrow0 + r) * Dm + hoff + c4 * 4];
        uint32_t* dst = &Qs[r * QPAD + c4 * 4];
        dst[0] = f2tf(v.x * qscale); dst[1] = f2tf(v.y * qscale);
        dst[2] = f2tf(v.z * qscale); dst[3] = f2tf(v.w * qscale);
    }

    float o[2][8][4];
#pragma unroll
    for (int mi = 0; mi < 2; mi++)
#pragma unroll
        for (int ni = 0; ni < 8; ni++)
#pragma unroll
            for (int e = 0; e < 4; e++) o[mi][ni][e] = 0.f;
    float mr[2][2] = {{-1e30f, -1e30f}, {-1e30f, -1e30f}};
    float lr[2][2] = {{0.f, 0.f}, {0.f, 0.f}};

    for (int t = 0; t < LKV / 64; t++) {
        __syncthreads();   // previous tile's P/V reads complete
        size_t kv0 = (size_t)bb * LKV + t * 64;
#pragma unroll
        for (int it = 0; it < 16; it++) {
            int f = it * 64 + tid;
            int r = f >> 4, c4 = f & 15;
            size_t gi = (kv0 + r) * Dm + hoff + c4 * 4;
            float4 kv_ = *(const float4*)&Km[gi];
            uint32_t* kd = &KP[r * QPAD + c4 * 4];
            kd[0] = f2tf(kv_.x); kd[1] = f2tf(kv_.y);
            kd[2] = f2tf(kv_.z); kd[3] = f2tf(kv_.w);
            float4 vv = *(const float4*)&Vm[gi];
            uint32_t* vd = &Vs[r * VPAD + c4 * 4];
            vd[0] = f2tf(vv.x); vd[1] = f2tf(vv.y);
            vd[2] = f2tf(vv.z); vd[3] = f2tf(vv.w);
        }
        __syncthreads();

        // ---- S = Q @ K^T ----
        float s[2][8][4];
#pragma unroll
        for (int mi = 0; mi < 2; mi++)
#pragma unroll
            for (int ni = 0; ni < 8; ni++)
#pragma unroll
                for (int e = 0; e < 4; e++) s[mi][ni][e] = 0.f;
#pragma unroll
        for (int ks = 0; ks < 8; ks++) {
            uint32_t a[2][4];
#pragma unroll
            for (int mi = 0; mi < 2; mi++) {
                const uint32_t* p = &Qs[(mb + mi * 16 + g) * QPAD + ks * 8 + qd];
                a[mi][0] = p[0]; a[mi][1] = p[8 * QPAD];
                a[mi][2] = p[4]; a[mi][3] = p[8 * QPAD + 4];
            }
#pragma unroll
            for (int ni = 0; ni < 8; ni++) {
                uint32_t b0 = KP[(ni * 8 + g) * QPAD + ks * 8 + qd];
                uint32_t b1 = KP[(ni * 8 + g) * QPAD + ks * 8 + qd + 4];
#pragma unroll
                for (int mi = 0; mi < 2; mi++)
                    mma_tf32(s[mi][ni], a[mi][0], a[mi][1], a[mi][2], a[mi][3], b0, b1);
            }
        }

        // ---- online softmax per mi-subtile ----
        float es[2][2];
#pragma unroll
        for (int mi = 0; mi < 2; mi++) {
            float mx0 = -1e30f, mx1 = -1e30f;
#pragma unroll
            for (int ni = 0; ni < 8; ni++) {
                mx0 = fmaxf(mx0, fmaxf(s[mi][ni][0], s[mi][ni][1]));
                mx1 = fmaxf(mx1, fmaxf(s[mi][ni][2], s[mi][ni][3]));
            }
            mx0 = fmaxf(mx0, __shfl_xor_sync(~0u, mx0, 1));
            mx0 = fmaxf(mx0, __shfl_xor_sync(~0u, mx0, 2));
            mx1 = fmaxf(mx1, __shfl_xor_sync(~0u, mx1, 1));
            mx1 = fmaxf(mx1, __shfl_xor_sync(~0u, mx1, 2));
            float mn0 = fmaxf(mr[mi][0], mx0), mn1 = fmaxf(mr[mi][1], mx1);
            float sum0 = 0.f, sum1 = 0.f;
#pragma unroll
            for (int ni = 0; ni < 8; ni++) {
                s[mi][ni][0] = ex2(s[mi][ni][0] - mn0);
                s[mi][ni][1] = ex2(s[mi][ni][1] - mn0);
                s[mi][ni][2] = ex2(s[mi][ni][2] - mn1);
                s[mi][ni][3] = ex2(s[mi][ni][3] - mn1);
                sum0 += s[mi][ni][0] + s[mi][ni][1];
                sum1 += s[mi][ni][2] + s[mi][ni][3];
            }
            sum0 += __shfl_xor_sync(~0u, sum0, 1); sum0 += __shfl_xor_sync(~0u, sum0, 2);
            sum1 += __shfl_xor_sync(~0u, sum1, 1); sum1 += __shfl_xor_sync(~0u, sum1, 2);
            es[mi][0] = ex2(mr[mi][0] - mn0); es[mi][1] = ex2(mr[mi][1] - mn1);
            mr[mi][0] = mn0; mr[mi][1] = mn1;
            lr[mi][0] = lr[mi][0] * es[mi][0] + sum0;
            lr[mi][1] = lr[mi][1] * es[mi][1] + sum1;
#pragma unroll
            for (int ni = 0; ni < 8; ni++) {
                o[mi][ni][0] *= es[mi][0]; o[mi][ni][1] *= es[mi][0];
                o[mi][ni][2] *= es[mi][1]; o[mi][ni][3] *= es[mi][1];
            }
        }

        __syncthreads();   // both warps finished reading K before P overwrite
#pragma unroll
        for (int mi = 0; mi < 2; mi++)
#pragma unroll
            for (int ni = 0; ni < 8; ni++) {
                int r0 = (mb + mi * 16 + g) * QPAD + ni * 8 + 2 * qd;
                KP[r0]                 = f2tf(s[mi][ni][0]);
                KP[r0 + 1]             = f2tf(s[mi][ni][1]);
                KP[r0 + 8 * QPAD]      = f2tf(s[mi][ni][2]);
                KP[r0 + 8 * QPAD + 1]  = f2tf(s[mi][ni][3]);
            }
        __syncwarp();      // each warp reads only its own P rows

        // ---- O += P @ V ----
#pragma unroll
        for (int ks = 0; ks < 8; ks++) {
            uint32_t a[2][4];
#pragma unroll
            for (int mi = 0; mi < 2; mi++) {
                const uint32_t* p = &KP[(mb + mi * 16 + g) * QPAD + ks * 8 + qd];
                a[mi][0] = p[0]; a[mi][1] = p[8 * QPAD];
                a[mi][2] = p[4]; a[mi][3] = p[8 * QPAD + 4];
            }
#pragma unroll
            for (int ni = 0; ni < 8; ni++) {
                uint32_t b0 = Vs[(ks * 8 + qd) * VPAD + ni * 8 + g];
                uint32_t b1 = Vs[(ks * 8 + qd + 4) * VPAD + ni * 8 + g];
#pragma unroll
                for (int mi = 0; mi < 2; mi++)
                    mma_tf32(o[mi][ni], a[mi][0], a[mi][1], a[mi][2], a[mi][3], b0, b1);
            }
        }
    }

#pragma unroll
    for (int mi = 0; mi < 2; mi++) {
        float inv0 = 1.f / lr[mi][0], inv1 = 1.f / lr[mi][1];
        int r0 = mb + mi * 16 + g;
#pragma unroll
        for (int ni = 0; ni < 8; ni++) {
            int ncol = hoff + ni * 8 + 2 * qd;
            *(float2*)&Om[(qrow0 + r0) * Dm + ncol] =
                make_float2(o[mi][ni][0] * inv0, o[mi][ni][1] * inv0);
            *(float2*)&Om[(qrow0 + r0 + 8) * Dm + ncol] =
                make_float2(o[mi][ni][2] * inv1, o[mi][ni][3] * inv1);
        }
    }
}

// ---------------- host orchestration ----------------
extern "C" void kernel_launch(void* const* d_in, const int* in_sizes, int n_in,
                              void* d_out, int out_size) {
    const float* hs  = (const float*)d_in[0];
    const float* hpe = (const float*)d_in[1];
    const float* fs  = (const float*)d_in[2];
    const float* fpe = (const float*)d_in[3];
    const float* os_ = (const float*)d_in[4];
    const float* ope = (const float*)d_in[5];
    const float* f_Wq = (const float*)d_in[6],  *f_Wk = (const float*)d_in[7];
    const float* f_Wv = (const float*)d_in[8],  *f_Wo = (const float*)d_in[9];
    const float* f_bq = (const float*)d_in[10], *f_bk = (const float*)d_in[11];
    const float* f_bv = (const float*)d_in[12], *f_bo = (const float*)d_in[13];
    const float* f_g  = (const float*)d_in[14], *f_b  = (const float*)d_in[15];
    const float* o_Wq = (const float*)d_in[16], *o_Wk = (const float*)d_in[17];
    const float* o_Wv = (const float*)d_in[18], *o_Wo = (const float*)d_in[19];
    const float* o_bq = (const float*)d_in[20], *o_bk = (const float*)d_in[21];
    const float* o_bv = (const float*)d_in[22], *o_bo = (const float*)d_in[23];
    const float* o_g  = (const float*)d_in[24], *o_b  = (const float*)d_in[25];
    const float* W1 = (const float*)d_in[26], *b1 = (const float*)d_in[27];
    const float* W2 = (const float*)d_in[28], *b2 = (const float*)d_in[29];
    const float* n3g = (const float*)d_in[30], *n3b = (const float*)d_in[31];
    float* out = (float*)d_out;

    float *ln, *Qp, *Kp, *Vp, *at, *x, *h1;
    cudaGetSymbolAddress((void**)&ln, g_ln);
    cudaGetSymbolAddress((void**)&Qp, g_Q);
    cudaGetSymbolAddress((void**)&Kp, g_K);
    cudaGetSymbolAddress((void**)&Vp, g_V);
    cudaGetSymbolAddress((void**)&at, g_attn);
    cudaGetSymbolAddress((void**)&x,  g_x);
    cudaGetSymbolAddress((void**)&h1, g_h1);

    cudaFuncSetAttribute(tgemm_k<false,false,false>, cudaFuncAttributeMaxDynamicSharedMemorySize, GEMM_SMEM);
    cudaFuncSetAttribute(tgemm_k<true, false,false>, cudaFuncAttributeMaxDynamicSharedMemorySize, GEMM_SMEM);
    cudaFuncSetAttribute(tgemm_k<false,false,true >, cudaFuncAttributeMaxDynamicSharedMemorySize, GEMM_SMEM);
    cudaFuncSetAttribute(tgemm_k<false,true, false>, cudaFuncAttributeMaxDynamicSharedMemorySize, GEMM_SMEM);
    cudaFuncSetAttribute(fattn_k, cudaFuncAttributeMaxDynamicSharedMemorySize, ATTN_SMEM);

    const int nkv4 = MKV * Dm / 4;
    dim3 g_qd(Dm / 128, MQ / 128);     // (4,16)
    dim3 g_kvd(Dm / 128, MKV / 128);   // (4,64)
    dim3 g_ffn1(Ff / 128, MQ / 128);   // (16,16)
    dim3 g_attn(LQ / 64, NH, Bc);      // (16,8,2)

    // passthrough outputs
    copy_k<<<nkv4 / 256, 256>>>(fs,  out + (size_t)MQ * Dm,                    nkv4);
    copy_k<<<nkv4 / 256, 256>>>(os_, out + (size_t)MQ * Dm + (size_t)MKV * Dm, nkv4);

    // ---- frame cross-attention sublayer ----
    ln_pe_k<<<MQ, 128>>>(hs, f_g, f_b, hpe, ln);
    tgemm_k<false,false,false><<<g_qd,  256, GEMM_SMEM>>>(ln, nullptr, f_Wq, f_bq, nullptr, Qp, MQ,  Dm, Dm);
    tgemm_k<true, false,false><<<g_kvd, 256, GEMM_SMEM>>>(fs, fpe,     f_Wk, f_bk, nullptr, Kp, MKV, Dm, Dm);
    tgemm_k<false,false,false><<<g_kvd, 256, GEMM_SMEM>>>(fs, nullptr, f_Wv, f_bv, nullptr, Vp, MKV, Dm, Dm);
    fattn_k<<<g_attn, 64, ATTN_SMEM>>>(Qp, Kp, Vp, at);
    tgemm_k<false,false,true><<<g_qd, 256, GEMM_SMEM>>>(at, nullptr, f_Wo, f_bo, hs, x, MQ, Dm, Dm);

    // ---- object cross-attention sublayer ----
    ln_pe_k<<<MQ, 128>>>(x, o_g, o_b, hpe, ln);
    tgemm_k<false,false,false><<<g_qd,  256, GEMM_SMEM>>>(ln,  nullptr, o_Wq, o_bq, nullptr, Qp, MQ,  Dm, Dm);
    tgemm_k<true, false,false><<<g_kvd, 256, GEMM_SMEM>>>(os_, ope,     o_Wk, o_bk, nullptr, Kp, MKV, Dm, Dm);
    tgemm_k<false,false,false><<<g_kvd, 256, GEMM_SMEM>>>(os_, nullptr, o_Wv, o_bv, nullptr, Vp, MKV, Dm, Dm);
    fattn_k<<<g_attn, 64, ATTN_SMEM>>>(Qp, Kp, Vp, at);
    tgemm_k<false,false,true><<<g_qd, 256, GEMM_SMEM>>>(at, nullptr, o_Wo, o_bo, x, x, MQ, Dm, Dm);

    // ---- FFN sublayer ----
    ln_pe_k<<<MQ, 128>>>(x, n3g, n3b, nullptr, ln);
    tgemm_k<false,true, false><<<g_ffn1, 256, GEMM_SMEM>>>(ln, nullptr, W1, b1, nullptr, h1, MQ, Ff, Dm);
    tgemm_k<false,false,true ><<<g_qd,   256, GEMM_SMEM>>>(h1, nullptr, W2, b2, x, out, MQ, Dm, Ff);
}

// round 5
// speedup vs baseline: 3.3067x; 1.3887x over previous
#include <cuda_runtime.h>
#include <cstdint>

// ---------------- problem dims (fixed) ----------------
#define Bc   2
#define LQ   1024
#define LKV  4096
#define Dm   512
#define NH   8
#define DHd  64
#define Ff   2048
#define MQ   (Bc*LQ)    // 2048
#define MKV  (Bc*LKV)   // 8192
#define SPLIT 4

// ---------------- scratch ----------------
__device__ float g_ln  [MQ*Dm];
__device__ float g_Q   [MQ*Dm];
__device__ float g_K   [MKV*Dm];
__device__ float g_V   [MKV*Dm];
__device__ float g_attn[MQ*Dm];
__device__ float g_x   [MQ*Dm];
__device__ float g_h1  [MQ*Ff];
__device__ float g_kv  [MKV*Dm];
__device__ float g_fsr [MKV*Dm];
__device__ float g_osr [MKV*Dm];
__device__ float g_Wr  [4*1024*1024];          // 8x256K squares + W1(1M) + W2(1M)
__device__ float g_part[SPLIT*MQ*Dm];
__device__ float g_ml  [SPLIT*MQ*NH*2];

// ---------------- helpers ----------------
__device__ __forceinline__ uint32_t f2tf(float x) {
    uint32_t r; asm("cvt.rna.tf32.f32 %0, %1;" : "=r"(r) : "f"(x)); return r;
}
__device__ __forceinline__ float rtf(float x) { return __uint_as_float(f2tf(x)); }
__device__ __forceinline__ void mma_tf32(float c[4],
    uint32_t a0, uint32_t a1, uint32_t a2, uint32_t a3, uint32_t b0, uint32_t b1) {
    asm("mma.sync.aligned.m16n8k8.row.col.f32.tf32.tf32.f32 "
        "{%0,%1,%2,%3},{%4,%5,%6,%7},{%8,%9},{%0,%1,%2,%3};"
        : "+f"(c[0]), "+f"(c[1]), "+f"(c[2]), "+f"(c[3])
        : "r"(a0), "r"(a1), "r"(a2), "r"(a3), "r"(b0), "r"(b1));
}
__device__ __forceinline__ float ex2(float x) {
    float y; asm("ex2.approx.f32 %0, %1;" : "=f"(y) : "f"(x)); return y;
}
__device__ __forceinline__ void cpa16(uint32_t dst, const void* src) {
    asm volatile("cp.async.cg.shared.global [%0], [%1], 16;" :: "r"(dst), "l"(src));
}
__device__ __forceinline__ void cpa_commit() {
    asm volatile("cp.async.commit_group;" ::: "memory");
}
template <int N> __device__ __forceinline__ void cpa_wait() {
    asm volatile("cp.async.wait_group %0;" :: "n"(N) : "memory");
}

// ---------------- elementwise ----------------
__global__ void copy_k(const float* __restrict__ a, float* __restrict__ c, int n4) {
    int i = blockIdx.x * blockDim.x + threadIdx.x;
    if (i < n4) ((float4*)c)[i] = ((const float4*)a)[i];
}
__global__ void roundcp_k(const float* __restrict__ a, float* __restrict__ c, int n4) {
    int i = blockIdx.x * blockDim.x + threadIdx.x;
    if (i < n4) {
        float4 v = ((const float4*)a)[i];
        v.x = rtf(v.x); v.y = rtf(v.y); v.z = rtf(v.z); v.w = rtf(v.w);
        ((float4*)c)[i] = v;
    }
}
struct Ptr8 { const float* p[8]; };
__global__ void round8_k(Ptr8 srcs, float* __restrict__ dst) {
    int m = blockIdx.y;
    const float4* s = (const float4*)srcs.p[m];
    int i = blockIdx.x * blockDim.x + threadIdx.x;
    float4 v = s[i];
    v.x = rtf(v.x); v.y = rtf(v.y); v.z = rtf(v.z); v.w = rtf(v.w);
    ((float4*)(dst + (size_t)m * 262144))[i] = v;
}
__global__ void add2r_k(const float* __restrict__ a, const float* __restrict__ b,
                        float* __restrict__ c, int n4) {
    int i = blockIdx.x * blockDim.x + threadIdx.x;
    if (i < n4) {
        float4 av = ((const float4*)a)[i];
        float4 bv = ((const float4*)b)[i];
        av.x = rtf(av.x + bv.x); av.y = rtf(av.y + bv.y);
        av.z = rtf(av.z + bv.z); av.w = rtf(av.w + bv.w);
        ((float4*)c)[i] = av;
    }
}

// ---------------- layernorm (+ optional pe), tf32-rounded output ----------------
__global__ void ln_pe_k(const float* __restrict__ x, const float* __restrict__ g,
                        const float* __restrict__ b, const float* __restrict__ pe,
                        float* __restrict__ out) {
    __shared__ float red[8];
    const int row = blockIdx.x, tid = threadIdx.x;
    const float* xr = x + (size_t)row * Dm;
    float4 xv = *(const float4*)&xr[tid * 4];
    float sum = xv.x + xv.y + xv.z + xv.w;
    float sq  = xv.x*xv.x + xv.y*xv.y + xv.z*xv.z + xv.w*xv.w;
#pragma unroll
    for (int off = 16; off > 0; off >>= 1) {
        sum += __shfl_xor_sync(0xffffffffu, sum, off);
        sq  += __shfl_xor_sync(0xffffffffu, sq,  off);
    }
    if ((tid & 31) == 0) { red[tid >> 5] = sum; red[4 + (tid >> 5)] = sq; }
    __syncthreads();
    sum = red[0] + red[1] + red[2] + red[3];
    sq  = red[4] + red[5] + red[6] + red[7];
    float mu   = sum * (1.0f / Dm);
    float var  = sq * (1.0f / Dm) - mu * mu;
    float rstd = rsqrtf(var + 1e-6f);
    float4 gv = *(const float4*)&g[tid * 4];
    float4 bv = *(const float4*)&b[tid * 4];
    float4 r;
    r.x = (xv.x - mu) * rstd * gv.x + bv.x;
    r.y = (xv.y - mu) * rstd * gv.y + bv.y;
    r.z = (xv.z - mu) * rstd * gv.z + bv.z;
    r.w = (xv.w - mu) * rstd * gv.w + bv.w;
    if (pe) {
        const float4 pv = *(const float4*)&pe[(size_t)row * Dm + tid * 4];
        r.x += pv.x; r.y += pv.y; r.z += pv.z; r.w += pv.w;
    }
    r.x = rtf(r.x); r.y = rtf(r.y); r.z = rtf(r.z); r.w = rtf(r.w);
    *(float4*)&out[(size_t)row * Dm + tid * 4] = r;
}

// ---------------- tf32 GEMM, cp.async 3-stage ----------------
// BM=64 BN=64 BK=32, 128 threads = 4 warps (2m x 2n), warp tile 32x32.
// Inputs A, W must already be tf32-rounded values.
#define GS_STAGE (64*36 + 32*72)               // words per stage
#define GEMM_SMEM (3 * GS_STAGE * 4)

template <bool RELU, bool RES, bool ROUND>
__global__ void __launch_bounds__(128, 4) tgemm2_k(
    const float* __restrict__ A, const float* __restrict__ W,
    const float* __restrict__ bias, const float* __restrict__ res,
    float* __restrict__ C, int M, int N, int K, float scale)
{
    extern __shared__ uint32_t smg[];
    const int tid = threadIdx.x, lane = tid & 31, w = tid >> 5;
    const int wm = w >> 1, wn = w & 1;
    const int g = lane >> 2, qd = lane & 3;
    const int m0 = blockIdx.y * 64, n0 = blockIdx.x * 64;
    const int ar = tid >> 3, ac4 = (tid & 7) * 4;
    const int br = tid >> 4, bc4 = (tid & 15) * 4;
    const uint32_t sbase = (uint32_t)__cvta_generic_to_shared(smg);

    const float* aSrc = A + (size_t)(m0 + ar) * K + ac4;
    const float* bSrc = W + (size_t)br * N + n0 + bc4;
    const int KT = K >> 5;

#pragma unroll
    for (int pre = 0; pre < 2; pre++) {
        uint32_t da = sbase + (pre * GS_STAGE + ar * 36 + ac4) * 4;
        uint32_t db = sbase + (pre * GS_STAGE + 64 * 36 + br * 72 + bc4) * 4;
        const float* sa = aSrc + pre * 32;
        const float* sb = bSrc + (size_t)pre * 32 * N;
#pragma unroll
        for (int it = 0; it < 4; it++) cpa16(da + it * 16 * 36 * 4, sa + (size_t)it * 16 * K);
#pragma unroll
        for (int it = 0; it < 4; it++) cpa16(db + it * 8 * 72 * 4, sb + (size_t)it * 8 * N);
        cpa_commit();
    }

    float acc[2][4][4] = {};   // [mi][ni], ni covers 4 x n8 within warp's 32 cols
    for (int kt = 0; kt < KT; kt++) {
        cpa_wait<1>();
        __syncthreads();
        if (kt + 2 < KT) {
            int s2 = (kt + 2) % 3;
            uint32_t da = sbase + (s2 * GS_STAGE + ar * 36 + ac4) * 4;
            uint32_t db = sbase + (s2 * GS_STAGE + 64 * 36 + br * 72 + bc4) * 4;
            const float* sa = aSrc + (kt + 2) * 32;
            const float* sb = bSrc + (size_t)(kt + 2) * 32 * N;
#pragma unroll
            for (int it = 0; it < 4; it++) cpa16(da + it * 16 * 36 * 4, sa + (size_t)it * 16 * K);
#pragma unroll
            for (int it = 0; it < 4; it++) cpa16(db + it * 8 * 72 * 4, sb + (size_t)it * 8 * N);
        }
        cpa_commit();
        const uint32_t* as = smg + (kt % 3) * GS_STAGE;
        const uint32_t* bs = as + 64 * 36;
#pragma unroll
        for (int ks = 0; ks < 4; ks++) {
            uint32_t af[2][4], bf[4][2];
#pragma unroll
            for (int mi = 0; mi < 2; mi++) {
                const uint32_t* p = &as[(wm * 32 + mi * 16 + g) * 36 + ks * 8 + qd];
                af[mi][0] = p[0]; af[mi][1] = p[8 * 36];
                af[mi][2] = p[4]; af[mi][3] = p[8 * 36 + 4];
            }
#pragma unroll
            for (int ni = 0; ni < 4; ni++) {
                const uint32_t* p = &bs[(ks * 8 + qd) * 72 + wn * 32 + ni * 8 + g];
                bf[ni][0] = p[0]; bf[ni][1] = p[4 * 72];
            }
#pragma unroll
            for (int mi = 0; mi < 2; mi++)
#pragma unroll
                for (int ni = 0; ni < 4; ni++)
                    mma_tf32(acc[mi][ni], af[mi][0], af[mi][1], af[mi][2], af[mi][3],
                             bf[ni][0], bf[ni][1]);
        }
    }

#pragma unroll
    for (int mi = 0; mi < 2; mi++) {
        int mrow = m0 + wm * 32 + mi * 16 + g;
#pragma unroll
        for (int ni = 0; ni < 4; ni++) {
            int ncol = n0 + wn * 32 + ni * 8 + 2 * qd;
            float2 bv = *(const float2*)&bias[ncol];
#pragma unroll
            for (int hh = 0; hh < 2; hh++) {
                size_t m = (size_t)(mrow + hh * 8);
                float2 v = make_float2(acc[mi][ni][hh * 2 + 0] + bv.x,
                                       acc[mi][ni][hh * 2 + 1] + bv.y);
                if (RELU) { v.x = fmaxf(v.x, 0.f); v.y = fmaxf(v.y, 0.f); }
                v.x *= scale; v.y *= scale;
                if (ROUND) { v.x = rtf(v.x); v.y = rtf(v.y); }
                if (RES) {
                    float2 rv = *(const float2*)&res[m * N + ncol];
                    v.x += rv.x; v.y += rv.y;
                }
                *(float2*)&C[m * N + ncol] = v;
            }
        }
    }
}

// ---------------- tf32 flash attention, kv-split ----------------
// 64 threads = 2 warps; q tile 64 (32 rows/warp), kv tile 64, dh 64.
// Q/K/V already tf32-rounded; Q pre-scaled by 0.125*log2(e).
// Writes UNNORMALIZED partial O and (m, l) per row/head/split.
#define QPAD 68
#define VPAD 72
#define ATTN_SMEM ((2 * 64 * QPAD + 64 * VPAD) * 4)
#define TKV (LKV / 64 / SPLIT)

__global__ void __launch_bounds__(64) fattn_k(
    const float* __restrict__ Qm, const float* __restrict__ Km,
    const float* __restrict__ Vm, float* __restrict__ part, float* __restrict__ ml)
{
    extern __shared__ uint32_t sm[];
    uint32_t* Qs = sm;
    uint32_t* KP = sm + 64 * QPAD;
    uint32_t* Vs = sm + 2 * 64 * QPAD;
    const uint32_t sbase = (uint32_t)__cvta_generic_to_shared(sm);

    const int tid = threadIdx.x;
    const int lane = tid & 31, w = tid >> 5;
    const int g = lane >> 2, qd = lane & 3;
    const int bb = blockIdx.z >> 2, sp = blockIdx.z & 3;
    const int hh = blockIdx.y, qt = blockIdx.x;
    const size_t qrow0 = (size_t)bb * LQ + qt * 64;
    const int hoff = hh * DHd;
    const int mb = w * 32;
    const int r0 = tid >> 4, c4 = (tid & 15) * 4;

    // Q fill (cp.async)
#pragma unroll
    for (int it = 0; it < 16; it++) {
        int r = it * 4 + r0;
        cpa16(sbase + (r * QPAD + c4) * 4, &Qm[(qrow0 + r) * Dm + hoff + c4]);
    }
    cpa_commit();

    float o[2][8][4] = {};
    float mr[2][2] = {{-1e30f, -1e30f}, {-1e30f, -1e30f}};
    float lr[2][2] = {{0.f, 0.f}, {0.f, 0.f}};

    for (int t = 0; t < TKV; t++) {
        __syncthreads();
        size_t kv0 = (size_t)bb * LKV + (sp * TKV + t) * 64;
#pragma unroll
        for (int it = 0; it < 16; it++) {
            int r = it * 4 + r0;
            size_t gi = (kv0 + r) * Dm + hoff + c4;
            cpa16(sbase + (64 * QPAD + r * QPAD + c4) * 4, &Km[gi]);
            cpa16(sbase + (2 * 64 * QPAD + r * VPAD + c4) * 4, &Vm[gi]);
        }
        cpa_commit();
        cpa_wait<0>();
        __syncthreads();

        // S = Q @ K^T
        float s[2][8][4] = {};
#pragma unroll
        for (int ks = 0; ks < 8; ks++) {
            uint32_t a[2][4];
#pragma unroll
            for (int mi = 0; mi < 2; mi++) {
                const uint32_t* p = &Qs[(mb + mi * 16 + g) * QPAD + ks * 8 + qd];
                a[mi][0] = p[0]; a[mi][1] = p[8 * QPAD];
                a[mi][2] = p[4]; a[mi][3] = p[8 * QPAD + 4];
            }
#pragma unroll
            for (int ni = 0; ni < 8; ni++) {
                uint32_t b0 = KP[(ni * 8 + g) * QPAD + ks * 8 + qd];
                uint32_t b1 = KP[(ni * 8 + g) * QPAD + ks * 8 + qd + 4];
#pragma unroll
                for (int mi = 0; mi < 2; mi++)
                    mma_tf32(s[mi][ni], a[mi][0], a[mi][1], a[mi][2], a[mi][3], b0, b1);
            }
        }

        // online softmax (base-2 domain)
        float es[2][2];
#pragma unroll
        for (int mi = 0; mi < 2; mi++) {
            float mx0 = -1e30f, mx1 = -1e30f;
#pragma unroll
            for (int ni = 0; ni < 8; ni++) {
                mx0 = fmaxf(mx0, fmaxf(s[mi][ni][0], s[mi][ni][1]));
                mx1 = fmaxf(mx1, fmaxf(s[mi][ni][2], s[mi][ni][3]));
            }
            mx0 = fmaxf(mx0, __shfl_xor_sync(~0u, mx0, 1));
            mx0 = fmaxf(mx0, __shfl_xor_sync(~0u, mx0, 2));
            mx1 = fmaxf(mx1, __shfl_xor_sync(~0u, mx1, 1));
            mx1 = fmaxf(mx1, __shfl_xor_sync(~0u, mx1, 2));
            float mn0 = fmaxf(mr[mi][0], mx0), mn1 = fmaxf(mr[mi][1], mx1);
            float sum0 = 0.f, sum1 = 0.f;
#pragma unroll
            for (int ni = 0; ni < 8; ni++) {
                s[mi][ni][0] = ex2(s[mi][ni][0] - mn0);
                s[mi][ni][1] = ex2(s[mi][ni][1] - mn0);
                s[mi][ni][2] = ex2(s[mi][ni][2] - mn1);
                s[mi][ni][3] = ex2(s[mi][ni][3] - mn1);
                sum0 += s[mi][ni][0] + s[mi][ni][1];
                sum1 += s[mi][ni][2] + s[mi][ni][3];
            }
            sum0 += __shfl_xor_sync(~0u, sum0, 1); sum0 += __shfl_xor_sync(~0u, sum0, 2);
            sum1 += __shfl_xor_sync(~0u, sum1, 1); sum1 += __shfl_xor_sync(~0u, sum1, 2);
            es[mi][0] = ex2(mr[mi][0] - mn0); es[mi][1] = ex2(mr[mi][1] - mn1);
            mr[mi][0] = mn0; mr[mi][1] = mn1;
            lr[mi][0] = lr[mi][0] * es[mi][0] + sum0;
            lr[mi][1] = lr[mi][1] * es[mi][1] + sum1;
#pragma unroll
            for (int ni = 0; ni < 8; ni++) {
                o[mi][ni][0] *= es[mi][0]; o[mi][ni][1] *= es[mi][0];
                o[mi][ni][2] *= es[mi][1]; o[mi][ni][3] *= es[mi][1];
            }
        }

        __syncthreads();   // both warps done reading K before P overwrite
#pragma unroll
        for (int mi = 0; mi < 2; mi++)
#pragma unroll
            for (int ni = 0; ni < 8; ni++) {
                int rI = (mb + mi * 16 + g) * QPAD + ni * 8 + 2 * qd;
                KP[rI]                = f2tf(s[mi][ni][0]);
                KP[rI + 1]            = f2tf(s[mi][ni][1]);
                KP[rI + 8 * QPAD]     = f2tf(s[mi][ni][2]);
                KP[rI + 8 * QPAD + 1] = f2tf(s[mi][ni][3]);
            }
        __syncwarp();

        // O += P @ V
#pragma unroll
        for (int ks = 0; ks < 8; ks++) {
            uint32_t a[2][4];
#pragma unroll
            for (int mi = 0; mi < 2; mi++) {
                const uint32_t* p = &KP[(mb + mi * 16 + g) * QPAD + ks * 8 + qd];
                a[mi][0] = p[0]; a[mi][1] = p[8 * QPAD];
                a[mi][2] = p[4]; a[mi][3] = p[8 * QPAD + 4];
            }
#pragma unroll
            for (int ni = 0; ni < 8; ni++) {
                uint32_t b0 = Vs[(ks * 8 + qd) * VPAD + ni * 8 + g];
                uint32_t b1 = Vs[(ks * 8 + qd + 4) * VPAD + ni * 8 + g];
#pragma unroll
                for (int mi = 0; mi < 2; mi++)
                    mma_tf32(o[mi][ni], a[mi][0], a[mi][1], a[mi][2], a[mi][3], b0, b1);
            }
        }
    }

    // write unnormalized partials + (m, l)
#pragma unroll
    for (int mi = 0; mi < 2; mi++) {
        int rloc = mb + mi * 16 + g;
#pragma unroll
        for (int ni = 0; ni < 8; ni++) {
            int ncol = hoff + ni * 8 + 2 * qd;
            *(float2*)&part[((size_t)sp * MQ + qrow0 + rloc) * Dm + ncol] =
                make_float2(o[mi][ni][0], o[mi][ni][1]);
            *(float2*)&part[((size_t)sp * MQ + qrow0 + rloc + 8) * Dm + ncol] =
                make_float2(o[mi][ni][2], o[mi][ni][3]);
        }
        if (qd == 0) {
            size_t b0 = (((size_t)sp * MQ + qrow0 + rloc) * NH + hh) * 2;
            ml[b0] = mr[mi][0]; ml[b0 + 1] = lr[mi][0];
            size_t b1 = (((size_t)sp * MQ + qrow0 + rloc + 8) * NH + hh) * 2;
            ml[b1] = mr[mi][1]; ml[b1 + 1] = lr[mi][1];
        }
    }
}

// ---------------- split combine ----------------
__global__ void comb_k(const float* __restrict__ part, const float* __restrict__ ml,
                       float* __restrict__ out) {
    int row = blockIdx.x, tid = threadIdx.x;
    int c = tid * 4, h = c >> 6;
    float m[SPLIT], l[SPLIT];
#pragma unroll
    for (int sp = 0; sp < SPLIT; sp++) {
        const float* p = &ml[(((size_t)sp * MQ + row) * NH + h) * 2];
        m[sp] = p[0]; l[sp] = p[1];
    }
    float M = fmaxf(fmaxf(m[0], m[1]), fmaxf(m[2], m[3]));
    float s[SPLIT], L = 0.f;
#pragma unroll
    for (int sp = 0; sp < SPLIT; sp++) { s[sp] = ex2(m[sp] - M); L += l[sp] * s[sp]; }
    float inv = 1.f / L;
    float4 a = make_float4(0.f, 0.f, 0.f, 0.f);
#pragma unroll
    for (int sp = 0; sp < SPLIT; sp++) {
        float4 v = *(const float4*)&part[((size_t)sp * MQ + row) * Dm + c];
        a.x += v.x * s[sp]; a.y += v.y * s[sp];
        a.z += v.z * s[sp]; a.w += v.w * s[sp];
    }
    a.x = rtf(a.x * inv); a.y = rtf(a.y * inv);
    a.z = rtf(a.z * inv); a.w = rtf(a.w * inv);
    *(float4*)&out[(size_t)row * Dm + c] = a;
}

// ---------------- host ----------------
extern "C" void kernel_launch(void* const* d_in, const int* in_sizes, int n_in,
                              void* d_out, int out_size) {
    const float* hs  = (const float*)d_in[0];
    const float* hpe = (const float*)d_in[1];
    const float* fs  = (const float*)d_in[2];
    const float* fpe = (const float*)d_in[3];
    const float* os_ = (const float*)d_in[4];
    const float* ope = (const float*)d_in[5];
    const float* f_Wq = (const float*)d_in[6],  *f_Wk = (const float*)d_in[7];
    const float* f_Wv = (const float*)d_in[8],  *f_Wo = (const float*)d_in[9];
    const float* f_bq = (const float*)d_in[10], *f_bk = (const float*)d_in[11];
    const float* f_bv = (const float*)d_in[12], *f_bo = (const float*)d_in[13];
    const float* f_g  = (const float*)d_in[14], *f_b  = (const float*)d_in[15];
    const float* o_Wq = (const float*)d_in[16], *o_Wk = (const float*)d_in[17];
    const float* o_Wv = (const float*)d_in[18], *o_Wo = (const float*)d_in[19];
    const float* o_bq = (const float*)d_in[20], *o_bk = (const float*)d_in[21];
    const float* o_bv = (const float*)d_in[22], *o_bo = (const float*)d_in[23];
    const float* o_g  = (const float*)d_in[24], *o_b  = (const float*)d_in[25];
    const float* W1 = (const float*)d_in[26], *b1 = (const float*)d_in[27];
    const float* W2 = (const float*)d_in[28], *b2 = (const float*)d_in[29];
    const float* n3g = (const float*)d_in[30], *n3b = (const float*)d_in[31];
    float* out = (float*)d_out;

    float *ln, *Qp, *Kp, *Vp, *at, *x, *h1, *kv, *fsr, *osr, *Wr, *pt, *ml;
    cudaGetSymbolAddress((void**)&ln, g_ln);
    cudaGetSymbolAddress((void**)&Qp, g_Q);
    cudaGetSymbolAddress((void**)&Kp, g_K);
    cudaGetSymbolAddress((void**)&Vp, g_V);
    cudaGetSymbolAddress((void**)&at, g_attn);
    cudaGetSymbolAddress((void**)&x,  g_x);
    cudaGetSymbolAddress((void**)&h1, g_h1);
    cudaGetSymbolAddress((void**)&kv, g_kv);
    cudaGetSymbolAddress((void**)&fsr, g_fsr);
    cudaGetSymbolAddress((void**)&osr, g_osr);
    cudaGetSymbolAddress((void**)&Wr, g_Wr);
    cudaGetSymbolAddress((void**)&pt, g_part);
    cudaGetSymbolAddress((void**)&ml, g_ml);

    cudaFuncSetAttribute(tgemm2_k<false,false,true >, cudaFuncAttributeMaxDynamicSharedMemorySize, GEMM_SMEM);
    cudaFuncSetAttribute(tgemm2_k<false,true ,false>, cudaFuncAttributeMaxDynamicSharedMemorySize, GEMM_SMEM);
    cudaFuncSetAttribute(tgemm2_k<true ,false,true >, cudaFuncAttributeMaxDynamicSharedMemorySize, GEMM_SMEM);
    cudaFuncSetAttribute(fattn_k, cudaFuncAttributeMaxDynamicSharedMemorySize, ATTN_SMEM);

    const int nkv4 = MKV * Dm / 4;
    const float qscale = 0.125f * 1.4426950408889634f;
    dim3 g_qd(Dm / 64, MQ / 64);      // (8,32)
    dim3 g_kvd(Dm / 64, MKV / 64);    // (8,128)
    dim3 g_ffn1(Ff / 64, MQ / 64);    // (32,32)
    dim3 g_attn(LQ / 64, NH, Bc * SPLIT);

    // rounded weight views
    const float *rf_Wq = Wr,             *rf_Wk = Wr + 262144,
                *rf_Wv = Wr + 2*262144,  *rf_Wo = Wr + 3*262144,
                *ro_Wq = Wr + 4*262144,  *ro_Wk = Wr + 5*262144,
                *ro_Wv = Wr + 6*262144,  *ro_Wo = Wr + 7*262144,
                *rW1   = Wr + 2097152,   *rW2   = Wr + 3145728;

    // passthrough outputs
    copy_k<<<nkv4 / 256, 256>>>(fs,  out + (size_t)MQ * Dm,                    nkv4);
    copy_k<<<nkv4 / 256, 256>>>(os_, out + (size_t)MQ * Dm + (size_t)MKV * Dm, nkv4);

    // pre-round weights and V-inputs
    Ptr8 p8; p8.p[0]=f_Wq; p8.p[1]=f_Wk; p8.p[2]=f_Wv; p8.p[3]=f_Wo;
    p8.p[4]=o_Wq; p8.p[5]=o_Wk; p8.p[6]=o_Wv; p8.p[7]=o_Wo;
    round8_k<<<dim3(256, 8), 256>>>(p8, Wr);
    roundcp_k<<<1024, 256>>>(W1, (float*)rW1, 262144);
    roundcp_k<<<1024, 256>>>(W2, (float*)rW2, 262144);
    roundcp_k<<<nkv4 / 256, 256>>>(fs,  fsr, nkv4);
    roundcp_k<<<nkv4 / 256, 256>>>(os_, osr, nkv4);

    // ---- frame cross-attention sublayer ----
    add2r_k<<<nkv4 / 256, 256>>>(fs, fpe, kv, nkv4);
    ln_pe_k<<<MQ, 128>>>(hs, f_g, f_b, hpe, ln);
    tgemm2_k<false,false,true ><<<g_qd,  128, GEMM_SMEM>>>(ln,  rf_Wq, f_bq, nullptr, Qp, MQ,  Dm, Dm, qscale);
    tgemm2_k<false,false,true ><<<g_kvd, 128, GEMM_SMEM>>>(kv,  rf_Wk, f_bk, nullptr, Kp, MKV, Dm, Dm, 1.f);
    tgemm2_k<false,false,true ><<<g_kvd, 128, GEMM_SMEM>>>(fsr, rf_Wv, f_bv, nullptr, Vp, MKV, Dm, Dm, 1.f);
    fattn_k<<<g_attn, 64, ATTN_SMEM>>>(Qp, Kp, Vp, pt, ml);
    comb_k<<<MQ, 128>>>(pt, ml, at);
    tgemm2_k<false,true ,false><<<g_qd, 128, GEMM_SMEM>>>(at, rf_Wo, f_bo, hs, x, MQ, Dm, Dm, 1.f);

    // ---- object cross-attention sublayer ----
    add2r_k<<<nkv4 / 256, 256>>>(os_, ope, kv, nkv4);
    ln_pe_k<<<MQ, 128>>>(x, o_g, o_b, hpe, ln);
    tgemm2_k<false,false,true ><<<g_qd,  128, GEMM_SMEM>>>(ln,  ro_Wq, o_bq, nullptr, Qp, MQ,  Dm, Dm, qscale);
    tgemm2_k<false,false,true ><<<g_kvd, 128, GEMM_SMEM>>>(kv,  ro_Wk, o_bk, nullptr, Kp, MKV, Dm, Dm, 1.f);
    tgemm2_k<false,false,true ><<<g_kvd, 128, GEMM_SMEM>>>(osr, ro_Wv, o_bv, nullptr, Vp, MKV, Dm, Dm, 1.f);
    fattn_k<<<g_attn, 64, ATTN_SMEM>>>(Qp, Kp, Vp, pt, ml);
    comb_k<<<MQ, 128>>>(pt, ml, at);
    tgemm2_k<false,true ,false><<<g_qd, 128, GEMM_SMEM>>>(at, ro_Wo, o_bo, x, x, MQ, Dm, Dm, 1.f);

    // ---- FFN sublayer ----
    ln_pe_k<<<MQ, 128>>>(x, n3g, n3b, nullptr, ln);
    tgemm2_k<true ,false,true ><<<g_ffn1, 128, GEMM_SMEM>>>(ln, rW1, b1, nullptr, h1, MQ, Ff, Dm, 1.f);
    tgemm2_k<false,true ,false><<<g_qd,   128, GEMM_SMEM>>>(h1, rW2, b2, x, out, MQ, Dm, Ff, 1.f);
}

// round 6
// speedup vs baseline: 5.0659x; 1.5320x over previous
#include <cuda_runtime.h>
#include <cuda_fp16.h>
#include <cstdint>

// ---------------- problem dims (fixed) ----------------
#define Bc   2
#define LQ   1024
#define LKV  4096
#define Dm   512
#define NH   8
#define DHd  64
#define Ff   2048
#define MQ   (Bc*LQ)    // 2048
#define MKV  (Bc*LKV)   // 8192
#define SPLIT 4
#define TKV  (LKV / 64 / SPLIT)   // 16

// ---------------- scratch (device globals) ----------------
__device__ __half hb_ln [MQ*Dm];
__device__ __half hb_kv [MKV*Dm];
__device__ __half hb_fsr[MKV*Dm];
__device__ __half hb_osr[MKV*Dm];
__device__ __half hb_Q  [MQ*Dm];
__device__ __half hb_K  [MKV*Dm];
__device__ __half hb_V  [MKV*Dm];
__device__ __half hb_at [MQ*Dm];
__device__ __half hb_h1 [MQ*Ff];
__device__ __half hb_WT [8*262144 + 2*1048576];  // 8 squares [512][512] + W1T[2048][512] + W2T[512][2048]
__device__ float  g_x   [MQ*Dm];
__device__ float  g_part[SPLIT*MQ*Dm];
__device__ float  g_ml  [SPLIT*MQ*NH*2];

// ---------------- helpers ----------------
__device__ __forceinline__ void mma_f16(float c[4], const uint32_t a[4],
                                        uint32_t b0, uint32_t b1) {
    asm("mma.sync.aligned.m16n8k16.row.col.f32.f16.f16.f32 "
        "{%0,%1,%2,%3},{%4,%5,%6,%7},{%8,%9},{%0,%1,%2,%3};"
        : "+f"(c[0]), "+f"(c[1]), "+f"(c[2]), "+f"(c[3])
        : "r"(a[0]), "r"(a[1]), "r"(a[2]), "r"(a[3]), "r"(b0), "r"(b1));
}
__device__ __forceinline__ void ldsm_x4(uint32_t& r0, uint32_t& r1, uint32_t& r2,
                                        uint32_t& r3, uint32_t addr) {
    asm volatile("ldmatrix.sync.aligned.m8n8.x4.shared.b16 {%0,%1,%2,%3},[%4];"
        : "=r"(r0), "=r"(r1), "=r"(r2), "=r"(r3) : "r"(addr));
}
__device__ __forceinline__ void ldsm_x4_t(uint32_t& r0, uint32_t& r1, uint32_t& r2,
                                          uint32_t& r3, uint32_t addr) {
    asm volatile("ldmatrix.sync.aligned.m8n8.x4.trans.shared.b16 {%0,%1,%2,%3},[%4];"
        : "=r"(r0), "=r"(r1), "=r"(r2), "=r"(r3) : "r"(addr));
}
__device__ __forceinline__ uint32_t packh2(float a, float b) {
    __half2 h = __floats2half2_rn(a, b);
    return *(uint32_t*)&h;
}
__device__ __forceinline__ float ex2(float x) {
    float y; asm("ex2.approx.f32 %0, %1;" : "=f"(y) : "f"(x)); return y;
}
__device__ __forceinline__ void cpa16(uint32_t dst, const void* src) {
    asm volatile("cp.async.cg.shared.global [%0], [%1], 16;" :: "r"(dst), "l"(src));
}
__device__ __forceinline__ void cpa_commit() {
    asm volatile("cp.async.commit_group;" ::: "memory");
}
template <int N> __device__ __forceinline__ void cpa_wait() {
    asm volatile("cp.async.wait_group %0;" :: "n"(N) : "memory");
}

// ---------------- elementwise ----------------
__global__ void copy_k(const float* __restrict__ a, float* __restrict__ c, int n4) {
    int i = blockIdx.x * blockDim.x + threadIdx.x;
    if (i < n4) ((float4*)c)[i] = ((const float4*)a)[i];
}
__global__ void cvth_k(const float* __restrict__ a, __half* __restrict__ c, int n4) {
    int i = blockIdx.x * blockDim.x + threadIdx.x;
    if (i < n4) {
        float4 v = ((const float4*)a)[i];
        uint2 o = { packh2(v.x, v.y), packh2(v.z, v.w) };
        ((uint2*)c)[i] = o;
    }
}
__global__ void add2h_k(const float* __restrict__ a, const float* __restrict__ b,
                        __half* __restrict__ c, int n4) {
    int i = blockIdx.x * blockDim.x + threadIdx.x;
    if (i < n4) {
        float4 av = ((const float4*)a)[i];
        float4 bv = ((const float4*)b)[i];
        uint2 o = { packh2(av.x + bv.x, av.y + bv.y), packh2(av.z + bv.z, av.w + bv.w) };
        ((uint2*)c)[i] = o;
    }
}
// transpose + convert: W [K][N] float  ->  WT [N][K] half
__global__ void tW_k(const float* __restrict__ W, __half* __restrict__ WT, int K, int N) {
    __shared__ float t[32][33];
    int n0 = blockIdx.x * 32, k0 = blockIdx.y * 32;
    int tx = threadIdx.x, ty = threadIdx.y;
#pragma unroll
    for (int j = 0; j < 32; j += 8)
        t[ty + j][tx] = W[(size_t)(k0 + ty + j) * N + n0 + tx];
    __syncthreads();
#pragma unroll
    for (int j = 0; j < 32; j += 8)
        WT[(size_t)(n0 + ty + j) * K + k0 + tx] = __float2half_rn(t[tx][ty + j]);
}

// ---------------- layernorm (+ optional pe), half output ----------------
__global__ void ln_pe_k(const float* __restrict__ x, const float* __restrict__ g,
                        const float* __restrict__ b, const float* __restrict__ pe,
                        __half* __restrict__ out) {
    __shared__ float red[8];
    const int row = blockIdx.x, tid = threadIdx.x;
    const float* xr = x + (size_t)row * Dm;
    float4 xv = *(const float4*)&xr[tid * 4];
    float sum = xv.x + xv.y + xv.z + xv.w;
    float sq  = xv.x*xv.x + xv.y*xv.y + xv.z*xv.z + xv.w*xv.w;
#pragma unroll
    for (int off = 16; off > 0; off >>= 1) {
        sum += __shfl_xor_sync(0xffffffffu, sum, off);
        sq  += __shfl_xor_sync(0xffffffffu, sq,  off);
    }
    if ((tid & 31) == 0) { red[tid >> 5] = sum; red[4 + (tid >> 5)] = sq; }
    __syncthreads();
    sum = red[0] + red[1] + red[2] + red[3];
    sq  = red[4] + red[5] + red[6] + red[7];
    float mu   = sum * (1.0f / Dm);
    float var  = sq * (1.0f / Dm) - mu * mu;
    float rstd = rsqrtf(var + 1e-6f);
    float4 gv = *(const float4*)&g[tid * 4];
    float4 bv = *(const float4*)&b[tid * 4];
    float4 r;
    r.x = (xv.x - mu) * rstd * gv.x + bv.x;
    r.y = (xv.y - mu) * rstd * gv.y + bv.y;
    r.z = (xv.z - mu) * rstd * gv.z + bv.z;
    r.w = (xv.w - mu) * rstd * gv.w + bv.w;
    if (pe) {
        const float4 pv = *(const float4*)&pe[(size_t)row * Dm + tid * 4];
        r.x += pv.x; r.y += pv.y; r.z += pv.z; r.w += pv.w;
    }
    uint2 o = { packh2(r.x, r.y), packh2(r.z, r.w) };
    *(uint2*)&out[(size_t)row * Dm + tid * 4] = o;
}

// ---------------- fp16 GEMM, cp.async 3-stage, ldmatrix ----------------
// C[M,N] = op(A[M,K]h @ WT[N,K]h^T + bias) ; BM=64 BN=64 BK=32, 128 thr (2m x 2n warps)
#define APITCH 40                              // halves per A/B smem row
#define GST    (2 * 64 * APITCH * 2)           // bytes per stage (A + B)
#define GEMM_SMEM (3 * GST)

template <bool RELU, bool RES, bool HOUT>
__global__ void __launch_bounds__(128) tgemm_k(
    const __half* __restrict__ A, const __half* __restrict__ WT,
    const float* __restrict__ bias, const float* __restrict__ res,
    void* __restrict__ C, int M, int N, int K, float scale)
{
    extern __shared__ __half smh[];
    const int tid = threadIdx.x, lane = tid & 31, w = tid >> 5;
    const int wm = w >> 1, wn = w & 1;
    const int g = lane >> 2, qd = lane & 3;
    const int m0 = blockIdx.y * 64, n0 = blockIdx.x * 64;
    const uint32_t sbase = (uint32_t)__cvta_generic_to_shared(smh);

    // fill assignments: 2 chunks each for A and B (64 rows x 4 x 16B)
    const int fr = tid >> 1, fc = (tid & 1) * 2;   // thread -> (row, first-chunk)
    const __half* aSrc = A  + (size_t)(m0 + fr) * K + fc * 8;
    const __half* bSrc = WT + (size_t)(n0 + fr) * K + fc * 8;
    const uint32_t aDst = sbase + (fr * APITCH + fc * 8) * 2;
    const uint32_t bDst = sbase + (64 * APITCH + fr * APITCH + fc * 8) * 2;

    // ldmatrix lane offsets (bytes from stage base)
    const int L = lane;
    const uint32_t aOff = ((wm * 32 + ((L >> 3) & 1) * 8 + (L & 7)) * APITCH
                           + (L >> 4) * 8) * 2;
    const uint32_t bOff = (64 * APITCH
                           + (wn * 32 + (L >> 4) * 8 + (L & 7)) * APITCH
                           + ((L >> 3) & 1) * 8) * 2;

    const int KT = K >> 5;
#pragma unroll
    for (int pre = 0; pre < 2; pre++) {
        const __half* sa = aSrc + pre * 32;
        const __half* sb = bSrc + pre * 32;
        uint32_t da = aDst + pre * GST, db = bDst + pre * GST;
        cpa16(da, sa); cpa16(da + 16, sa + 8);
        cpa16(db, sb); cpa16(db + 16, sb + 8);
        cpa_commit();
    }

    float acc[2][4][4] = {};
    for (int kt = 0; kt < KT; kt++) {
        cpa_wait<1>();
        __syncthreads();
        if (kt + 2 < KT) {
            int s2 = (kt + 2) % 3;
            const __half* sa = aSrc + (kt + 2) * 32;
            const __half* sb = bSrc + (kt + 2) * 32;
            uint32_t da = aDst + s2 * GST, db = bDst + s2 * GST;
            cpa16(da, sa); cpa16(da + 16, sa + 8);
            cpa16(db, sb); cpa16(db + 16, sb + 8);
        }
        cpa_commit();
        const uint32_t st = sbase + (kt % 3) * GST;
#pragma unroll
        for (int ks = 0; ks < 2; ks++) {
            uint32_t af[2][4], bf[4][2];
#pragma unroll
            for (int mi = 0; mi < 2; mi++)
                ldsm_x4(af[mi][0], af[mi][1], af[mi][2], af[mi][3],
                        st + aOff + (mi * 16 * APITCH + ks * 16) * 2);
#pragma unroll
            for (int p = 0; p < 2; p++) {
                uint32_t r0, r1, r2, r3;
                ldsm_x4(r0, r1, r2, r3, st + bOff + (p * 16 * APITCH + ks * 16) * 2);
                bf[2*p][0] = r0; bf[2*p][1] = r1;
                bf[2*p+1][0] = r2; bf[2*p+1][1] = r3;
            }
#pragma unroll
            for (int mi = 0; mi < 2; mi++)
#pragma unroll
                for (int ni = 0; ni < 4; ni++)
                    mma_f16(acc[mi][ni], af[mi], bf[ni][0], bf[ni][1]);
        }
    }

#pragma unroll
    for (int mi = 0; mi < 2; mi++) {
        int mrow = m0 + wm * 32 + mi * 16 + g;
#pragma unroll
        for (int ni = 0; ni < 4; ni++) {
            int ncol = n0 + wn * 32 + ni * 8 + 2 * qd;
            float2 bv = *(const float2*)&bias[ncol];
#pragma unroll
            for (int hh = 0; hh < 2; hh++) {
                size_t m = (size_t)(mrow + hh * 8);
                float vx = acc[mi][ni][hh * 2 + 0] + bv.x;
                float vy = acc[mi][ni][hh * 2 + 1] + bv.y;
                if (RELU) { vx = fmaxf(vx, 0.f); vy = fmaxf(vy, 0.f); }
                vx *= scale; vy *= scale;
                if (HOUT) {
                    *(__half2*)((__half*)C + m * N + ncol) = __floats2half2_rn(vx, vy);
                } else {
                    if (RES) {
                        float2 rv = *(const float2*)&res[m * N + ncol];
                        vx += rv.x; vy += rv.y;
                    }
                    *(float2*)((float*)C + m * N + ncol) = make_float2(vx, vy);
                }
            }
        }
    }
}

// ---------------- fp16 flash attention, kv-split, double-buffered ----------------
// 64 threads = 2 warps; q tile 64 (32 rows/warp), kv tile 64, dh 64.
#define FPITCH 72                               // halves per smem row
#define QB  (64 * FPITCH * 2)                   // bytes per 64x64 tile
#define ATTN_SMEM (5 * QB)                      // Q + 2x(K,V)

__global__ void __launch_bounds__(64) fattn_k(
    const __half* __restrict__ Qm, const __half* __restrict__ Km,
    const __half* __restrict__ Vm, float* __restrict__ part, float* __restrict__ ml)
{
    extern __shared__ __half smf[];
    const uint32_t sbase = (uint32_t)__cvta_generic_to_shared(smf);
    const uint32_t sQ = sbase;

    const int tid = threadIdx.x;
    const int lane = tid & 31, w = tid >> 5;
    const int g = lane >> 2, qd = lane & 3;
    const int bb = blockIdx.z >> 2, sp = blockIdx.z & 3;
    const int hh = blockIdx.y, qt = blockIdx.x;
    const size_t qrow0 = (size_t)bb * LQ + qt * 64;
    const int hoff = hh * DHd;
    const int mb = w * 32;
    const int L = lane;

    // fill: 8 chunks per thread (64 rows x 8 x 16B / 64 threads)
    const int frr = tid >> 3, fcc = (tid & 7);    // base row group, chunk
    // Q fill
#pragma unroll
    for (int it = 0; it < 8; it++) {
        int r = frr + it * 8;
        cpa16(sQ + (r * FPITCH + fcc * 8) * 2, &Qm[(qrow0 + r) * Dm + hoff + fcc * 8]);
    }
    // KV tile 0
    size_t kvb = (size_t)bb * LKV + (size_t)sp * TKV * 64;
#pragma unroll
    for (int it = 0; it < 8; it++) {
        int r = frr + it * 8;
        size_t gi = (kvb + r) * Dm + hoff + fcc * 8;
        cpa16(sQ + QB + (r * FPITCH + fcc * 8) * 2,     &Km[gi]);
        cpa16(sQ + 2 * QB + (r * FPITCH + fcc * 8) * 2, &Vm[gi]);
    }
    cpa_commit();
    // KV tile 1
#pragma unroll
    for (int it = 0; it < 8; it++) {
        int r = frr + it * 8;
        size_t gi = (kvb + 64 + r) * Dm + hoff + fcc * 8;
        cpa16(sQ + 3 * QB + (r * FPITCH + fcc * 8) * 2, &Km[gi]);
        cpa16(sQ + 4 * QB + (r * FPITCH + fcc * 8) * 2, &Vm[gi]);
    }
    cpa_commit();

    // ldmatrix lane offsets (bytes from tile base)
    const uint32_t qOff = ((mb + ((L >> 3) & 1) * 8 + (L & 7)) * FPITCH + (L >> 4) * 8) * 2;
    const uint32_t kOff = (((L >> 4) * 8 + (L & 7)) * FPITCH + ((L >> 3) & 1) * 8) * 2;
    const uint32_t vOff = ((L & 15) * FPITCH + (L >> 4) * 8) * 2;

    uint32_t aq[2][4][4];
    float o[2][8][4] = {};
    float mr[2][2] = {{-1e30f, -1e30f}, {-1e30f, -1e30f}};
    float lr[2][2] = {{0.f, 0.f}, {0.f, 0.f}};

    for (int t = 0; t < TKV; t++) {
        cpa_wait<1>();
        __syncthreads();
        if (t == 0) {
#pragma unroll
            for (int mi = 0; mi < 2; mi++)
#pragma unroll
                for (int ks = 0; ks < 4; ks++)
                    ldsm_x4(aq[mi][ks][0], aq[mi][ks][1], aq[mi][ks][2], aq[mi][ks][3],
                            sQ + qOff + (mi * 16 * FPITCH + ks * 16) * 2);
        }
        const uint32_t sK = sQ + QB + (t & 1) * 2 * QB;
        const uint32_t sV = sK + QB;

        // ---- S = Q @ K^T ----
        float s[2][8][4] = {};
#pragma unroll
        for (int ks = 0; ks < 4; ks++) {
            uint32_t kb[8][2];
#pragma unroll
            for (int p = 0; p < 4; p++) {
                uint32_t r0, r1, r2, r3;
                ldsm_x4(r0, r1, r2, r3, sK + kOff + (p * 16 * FPITCH + ks * 16) * 2);
                kb[2*p][0] = r0; kb[2*p][1] = r1;
                kb[2*p+1][0] = r2; kb[2*p+1][1] = r3;
            }
#pragma unroll
            for (int mi = 0; mi < 2; mi++)
#pragma unroll
                for (int ni = 0; ni < 8; ni++)
                    mma_f16(s[mi][ni], aq[mi][ks], kb[ni][0], kb[ni][1]);
        }

        // ---- online softmax (base-2 domain; qscale*log2e folded into Q) ----
        float es[2][2];
#pragma unroll
        for (int mi = 0; mi < 2; mi++) {
            float mx0 = -1e30f, mx1 = -1e30f;
#pragma unroll
            for (int ni = 0; ni < 8; ni++) {
                mx0 = fmaxf(mx0, fmaxf(s[mi][ni][0], s[mi][ni][1]));
                mx1 = fmaxf(mx1, fmaxf(s[mi][ni][2], s[mi][ni][3]));
            }
            mx0 = fmaxf(mx0, __shfl_xor_sync(~0u, mx0, 1));
            mx0 = fmaxf(mx0, __shfl_xor_sync(~0u, mx0, 2));
            mx1 = fmaxf(mx1, __shfl_xor_sync(~0u, mx1, 1));
            mx1 = fmaxf(mx1, __shfl_xor_sync(~0u, mx1, 2));
            float mn0 = fmaxf(mr[mi][0], mx0), mn1 = fmaxf(mr[mi][1], mx1);
            float sum0 = 0.f, sum1 = 0.f;
#pragma unroll
            for (int ni = 0; ni < 8; ni++) {
                s[mi][ni][0] = ex2(s[mi][ni][0] - mn0);
                s[mi][ni][1] = ex2(s[mi][ni][1] - mn0);
                s[mi][ni][2] = ex2(s[mi][ni][2] - mn1);
                s[mi][ni][3] = ex2(s[mi][ni][3] - mn1);
                sum0 += s[mi][ni][0] + s[mi][ni][1];
                sum1 += s[mi][ni][2] + s[mi][ni][3];
            }
            sum0 += __shfl_xor_sync(~0u, sum0, 1); sum0 += __shfl_xor_sync(~0u, sum0, 2);
            sum1 += __shfl_xor_sync(~0u, sum1, 1); sum1 += __shfl_xor_sync(~0u, sum1, 2);
            es[mi][0] = ex2(mr[mi][0] - mn0); es[mi][1] = ex2(mr[mi][1] - mn1);
            mr[mi][0] = mn0; mr[mi][1] = mn1;
            lr[mi][0] = lr[mi][0] * es[mi][0] + sum0;
            lr[mi][1] = lr[mi][1] * es[mi][1] + sum1;
#pragma unroll
            for (int ni = 0; ni < 8; ni++) {
                o[mi][ni][0] *= es[mi][0]; o[mi][ni][1] *= es[mi][0];
                o[mi][ni][2] *= es[mi][1]; o[mi][ni][3] *= es[mi][1];
            }
        }

        // ---- O += P @ V (P packed directly from registers) ----
#pragma unroll
        for (int ks = 0; ks < 4; ks++) {
            uint32_t vb[8][2];
#pragma unroll
            for (int j = 0; j < 4; j++) {
                uint32_t r0, r1, r2, r3;
                ldsm_x4_t(r0, r1, r2, r3, sV + vOff + (ks * 16 * FPITCH + j * 16) * 2);
                vb[2*j][0] = r0; vb[2*j][1] = r1;
                vb[2*j+1][0] = r2; vb[2*j+1][1] = r3;
            }
            uint32_t ap[2][4];
#pragma unroll
            for (int mi = 0; mi < 2; mi++) {
                ap[mi][0] = packh2(s[mi][2*ks][0],   s[mi][2*ks][1]);
                ap[mi][1] = packh2(s[mi][2*ks][2],   s[mi][2*ks][3]);
                ap[mi][2] = packh2(s[mi][2*ks+1][0], s[mi][2*ks+1][1]);
                ap[mi][3] = packh2(s[mi][2*ks+1][2], s[mi][2*ks+1][3]);
            }
#pragma unroll
            for (int mi = 0; mi < 2; mi++)
#pragma unroll
                for (int ni = 0; ni < 8; ni++)
                    mma_f16(o[mi][ni], ap[mi], vb[ni][0], vb[ni][1]);
        }

        __syncthreads();   // all warps done reading buf before refill
        if (t + 2 < TKV) {
            size_t kv0 = kvb + (size_t)(t + 2) * 64;
            uint32_t dK = sQ + QB + (t & 1) * 2 * QB;
#pragma unroll
            for (int it = 0; it < 8; it++) {
                int r = frr + it * 8;
                size_t gi = (kv0 + r) * Dm + hoff + fcc * 8;
                cpa16(dK + (r * FPITCH + fcc * 8) * 2,      &Km[gi]);
                cpa16(dK + QB + (r * FPITCH + fcc * 8) * 2, &Vm[gi]);
            }
        }
        cpa_commit();
    }

    // write unnormalized partials + (m, l)
#pragma unroll
    for (int mi = 0; mi < 2; mi++) {
        int rloc = mb + mi * 16 + g;
#pragma unroll
        for (int ni = 0; ni < 8; ni++) {
            int ncol = hoff + ni * 8 + 2 * qd;
            *(float2*)&part[((size_t)sp * MQ + qrow0 + rloc) * Dm + ncol] =
                make_float2(o[mi][ni][0], o[mi][ni][1]);
            *(float2*)&part[((size_t)sp * MQ + qrow0 + rloc + 8) * Dm + ncol] =
                make_float2(o[mi][ni][2], o[mi][ni][3]);
        }
        if (qd == 0) {
            size_t b0 = (((size_t)sp * MQ + qrow0 + rloc) * NH + hh) * 2;
            ml[b0] = mr[mi][0]; ml[b0 + 1] = lr[mi][0];
            size_t b1 = (((size_t)sp * MQ + qrow0 + rloc + 8) * NH + hh) * 2;
            ml[b1] = mr[mi][1]; ml[b1 + 1] = lr[mi][1];
        }
    }
}

// ---------------- split combine (half output) ----------------
__global__ void comb_k(const float* __restrict__ part, const float* __restrict__ ml,
                       __half* __restrict__ out) {
    int row = blockIdx.x, tid = threadIdx.x;
    int c = tid * 4, h = c >> 6;
    float m[SPLIT], l[SPLIT];
#pragma unroll
    for (int sp = 0; sp < SPLIT; sp++) {
        const float* p = &ml[(((size_t)sp * MQ + row) * NH + h) * 2];
        m[sp] = p[0]; l[sp] = p[1];
    }
    float M = fmaxf(fmaxf(m[0], m[1]), fmaxf(m[2], m[3]));
    float s[SPLIT], Lh = 0.f;
#pragma unroll
    for (int sp = 0; sp < SPLIT; sp++) { s[sp] = ex2(m[sp] - M); Lh += l[sp] * s[sp]; }
    float inv = 1.f / Lh;
    float4 a = make_float4(0.f, 0.f, 0.f, 0.f);
#pragma unroll
    for (int sp = 0; sp < SPLIT; sp++) {
        float4 v = *(const float4*)&part[((size_t)sp * MQ + row) * Dm + c];
        a.x += v.x * s[sp]; a.y += v.y * s[sp];
        a.z += v.z * s[sp]; a.w += v.w * s[sp];
    }
    uint2 o = { packh2(a.x * inv, a.y * inv), packh2(a.z * inv, a.w * inv) };
    *(uint2*)&out[(size_t)row * Dm + c] = o;
}

// ---------------- host ----------------
extern "C" void kernel_launch(void* const* d_in, const int* in_sizes, int n_in,
                              void* d_out, int out_size) {
    const float* hs  = (const float*)d_in[0];
    const float* hpe = (const float*)d_in[1];
    const float* fs  = (const float*)d_in[2];
    const float* fpe = (const float*)d_in[3];
    const float* os_ = (const float*)d_in[4];
    const float* ope = (const float*)d_in[5];
    const float* f_Wq = (const float*)d_in[6],  *f_Wk = (const float*)d_in[7];
    const float* f_Wv = (const float*)d_in[8],  *f_Wo = (const float*)d_in[9];
    const float* f_bq = (const float*)d_in[10], *f_bk = (const float*)d_in[11];
    const float* f_bv = (const float*)d_in[12], *f_bo = (const float*)d_in[13];
    const float* f_g  = (const float*)d_in[14], *f_b  = (const float*)d_in[15];
    const float* o_Wq = (const float*)d_in[16], *o_Wk = (const float*)d_in[17];
    const float* o_Wv = (const float*)d_in[18], *o_Wo = (const float*)d_in[19];
    const float* o_bq = (const float*)d_in[20], *o_bk = (const float*)d_in[21];
    const float* o_bv = (const float*)d_in[22], *o_bo = (const float*)d_in[23];
    const float* o_g  = (const float*)d_in[24], *o_b  = (const float*)d_in[25];
    const float* W1 = (const float*)d_in[26], *b1 = (const float*)d_in[27];
    const float* W2 = (const float*)d_in[28], *b2 = (const float*)d_in[29];
    const float* n3g = (const float*)d_in[30], *n3b = (const float*)d_in[31];
    float* out = (float*)d_out;

    __half *ln, *kv, *fsr, *osr, *Qh, *Kh, *Vh, *at, *h1, *WT;
    float *x, *pt, *mlp;
    cudaGetSymbolAddress((void**)&ln,  hb_ln);
    cudaGetSymbolAddress((void**)&kv,  hb_kv);
    cudaGetSymbolAddress((void**)&fsr, hb_fsr);
    cudaGetSymbolAddress((void**)&osr, hb_osr);
    cudaGetSymbolAddress((void**)&Qh,  hb_Q);
    cudaGetSymbolAddress((void**)&Kh,  hb_K);
    cudaGetSymbolAddress((void**)&Vh,  hb_V);
    cudaGetSymbolAddress((void**)&at,  hb_at);
    cudaGetSymbolAddress((void**)&h1,  hb_h1);
    cudaGetSymbolAddress((void**)&WT,  hb_WT);
    cudaGetSymbolAddress((void**)&x,   g_x);
    cudaGetSymbolAddress((void**)&pt,  g_part);
    cudaGetSymbolAddress((void**)&mlp, g_ml);

    cudaFuncSetAttribute(tgemm_k<false,false,true >, cudaFuncAttributeMaxDynamicSharedMemorySize, GEMM_SMEM);
    cudaFuncSetAttribute(tgemm_k<true ,false,true >, cudaFuncAttributeMaxDynamicSharedMemorySize, GEMM_SMEM);
    cudaFuncSetAttribute(tgemm_k<false,true ,false>, cudaFuncAttributeMaxDynamicSharedMemorySize, GEMM_SMEM);
    cudaFuncSetAttribute(fattn_k, cudaFuncAttributeMaxDynamicSharedMemorySize, ATTN_SMEM);

    const int nkv4 = MKV * Dm / 4;
    const float qscale = 0.125f * 1.4426950408889634f;
    dim3 g_qd(Dm / 64, MQ / 64);      // (8,32)
    dim3 g_kvd(Dm / 64, MKV / 64);    // (8,128)
    dim3 g_ffn1(Ff / 64, MQ / 64);    // (32,32)
    dim3 g_attn(LQ / 64, NH, Bc * SPLIT);
    dim3 tblk(32, 8);

    // transposed half weight views (element offsets)
    __half *rf_Wq = WT,               *rf_Wk = WT + 262144,
           *rf_Wv = WT + 2*262144,    *rf_Wo = WT + 3*262144,
           *ro_Wq = WT + 4*262144,    *ro_Wk = WT + 5*262144,
           *ro_Wv = WT + 6*262144,    *ro_Wo = WT + 7*262144,
           *rW1   = WT + 8*262144,    *rW2   = WT + 8*262144 + 1048576;

    // passthrough outputs
    copy_k<<<nkv4 / 256, 256>>>(fs,  out + (size_t)MQ * Dm,                    nkv4);
    copy_k<<<nkv4 / 256, 256>>>(os_, out + (size_t)MQ * Dm + (size_t)MKV * Dm, nkv4);

    // weights -> transposed half
    tW_k<<<dim3(16,16), tblk>>>(f_Wq, rf_Wq, Dm, Dm);
    tW_k<<<dim3(16,16), tblk>>>(f_Wk, rf_Wk, Dm, Dm);
    tW_k<<<dim3(16,16), tblk>>>(f_Wv, rf_Wv, Dm, Dm);
    tW_k<<<dim3(16,16), tblk>>>(f_Wo, rf_Wo, Dm, Dm);
    tW_k<<<dim3(16,16), tblk>>>(o_Wq, ro_Wq, Dm, Dm);
    tW_k<<<dim3(16,16), tblk>>>(o_Wk, ro_Wk, Dm, Dm);
    tW_k<<<dim3(16,16), tblk>>>(o_Wv, ro_Wv, Dm, Dm);
    tW_k<<<dim3(16,16), tblk>>>(o_Wo, ro_Wo, Dm, Dm);
    tW_k<<<dim3(64,16), tblk>>>(W1, rW1, Dm, Ff);   // W1 [512][2048] -> [2048][512]
    tW_k<<<dim3(16,64), tblk>>>(W2, rW2, Ff, Dm);   // W2 [2048][512] -> [512][2048]

    // V-inputs -> half
    cvth_k<<<nkv4 / 256, 256>>>(fs,  fsr, nkv4);
    cvth_k<<<nkv4 / 256, 256>>>(os_, osr, nkv4);

    // ---- frame cross-attention sublayer ----
    add2h_k<<<nkv4 / 256, 256>>>(fs, fpe, kv, nkv4);
    ln_pe_k<<<MQ, 128>>>(hs, f_g, f_b, hpe, ln);
    tgemm_k<false,false,true ><<<g_qd,  128, GEMM_SMEM>>>(ln,  rf_Wq, f_bq, nullptr, Qh, MQ,  Dm, Dm, qscale);
    tgemm_k<false,false,true ><<<g_kvd, 128, GEMM_SMEM>>>(kv,  rf_Wk, f_bk, nullptr, Kh, MKV, Dm, Dm, 1.f);
    tgemm_k<false,false,true ><<<g_kvd, 128, GEMM_SMEM>>>(fsr, rf_Wv, f_bv, nullptr, Vh, MKV, Dm, Dm, 1.f);
    fattn_k<<<g_attn, 64, ATTN_SMEM>>>(Qh, Kh, Vh, pt, mlp);
    comb_k<<<MQ, 128>>>(pt, mlp, at);
    tgemm_k<false,true ,false><<<g_qd, 128, GEMM_SMEM>>>(at, rf_Wo, f_bo, hs, x, MQ, Dm, Dm, 1.f);

    // ---- object cross-attention sublayer ----
    add2h_k<<<nkv4 / 256, 256>>>(os_, ope, kv, nkv4);
    ln_pe_k<<<MQ, 128>>>(x, o_g, o_b, hpe, ln);
    tgemm_k<false,false,true ><<<g_qd,  128, GEMM_SMEM>>>(ln,  ro_Wq, o_bq, nullptr, Qh, MQ,  Dm, Dm, qscale);
    tgemm_k<false,false,true ><<<g_kvd, 128, GEMM_SMEM>>>(kv,  ro_Wk, o_bk, nullptr, Kh, MKV, Dm, Dm, 1.f);
    tgemm_k<false,false,true ><<<g_kvd, 128, GEMM_SMEM>>>(osr, ro_Wv, o_bv, nullptr, Vh, MKV, Dm, Dm, 1.f);
    fattn_k<<<g_attn, 64, ATTN_SMEM>>>(Qh, Kh, Vh, pt, mlp);
    comb_k<<<MQ, 128>>>(pt, mlp, at);
    tgemm_k<false,true ,false><<<g_qd, 128, GEMM_SMEM>>>(at, ro_Wo, o_bo, x, x, MQ, Dm, Dm, 1.f);

    // ---- FFN sublayer ----
    ln_pe_k<<<MQ, 128>>>(x, n3g, n3b, nullptr, ln);
    tgemm_k<true ,false,true ><<<g_ffn1, 128, GEMM_SMEM>>>(ln, rW1, b1, nullptr, h1, MQ, Ff, Dm, 1.f);
    tgemm_k<false,true ,false><<<g_qd,   128, GEMM_SMEM>>>(h1, rW2, b2, x, out, MQ, Dm, Ff, 1.f);
}

// round 11
// speedup vs baseline: 5.0708x; 1.0010x over previous
#include <cuda_runtime.h>
#include <cuda_fp16.h>
#include <cstdint>

// ---------------- problem dims (fixed) ----------------
#define Bc   2
#define LQ   1024
#define LKV  4096
#define Dm   512
#define NH   8
#define DHd  64
#define Ff   2048
#define MQ   (Bc*LQ)    // 2048
#define MKV  (Bc*LKV)   // 8192
#define SPLIT 2
#define TKV  (LKV / 64 / SPLIT)   // 32

// ---------------- scratch (device globals) ----------------
__device__ __half hb_ln [MQ*Dm];
__device__ __half hb_kvf[MKV*Dm];
__device__ __half hb_kvo[MKV*Dm];
__device__ __half hb_fsr[MKV*Dm];
__device__ __half hb_osr[MKV*Dm];
__device__ __half hb_Q  [MQ*Dm];
__device__ __half hb_K  [MKV*Dm];
__device__ __half hb_V  [MKV*Dm];
__device__ __half hb_at [MQ*Dm];
__device__ __half hb_h1 [MQ*Ff];
__device__ __half hb_WT [8*262144 + 2*1048576];
__device__ float  g_x   [MQ*Dm];
__device__ float  g_part[SPLIT*MQ*Dm];
__device__ float  g_ml  [SPLIT*MQ*NH*2];

// ---------------- helpers ----------------
__device__ __forceinline__ uint32_t packh2(float a, float b) {
    __half2 h = __floats2half2_rn(a, b);
    return *(uint32_t*)&h;
}
__device__ __forceinline__ float ex2(float x) {
    float y; asm("ex2.approx.f32 %0, %1;" : "=f"(y) : "f"(x)); return y;
}
__device__ __forceinline__ void cpa16(uint32_t dst, const void* src) {
    asm volatile("cp.async.cg.shared.global [%0], [%1], 16;" :: "r"(dst), "l"(src));
}
__device__ __forceinline__ void cpa_commit() {
    asm volatile("cp.async.commit_group;" ::: "memory");
}
template <int N> __device__ __forceinline__ void cpa_wait() {
    asm volatile("cp.async.wait_group %0;" :: "n"(N) : "memory");
}
__device__ __forceinline__ void mma_f16(float c[4], const uint32_t a[4],
                                        uint32_t b0, uint32_t b1) {
    asm("mma.sync.aligned.m16n8k16.row.col.f32.f16.f16.f32 "
        "{%0,%1,%2,%3},{%4,%5,%6,%7},{%8,%9},{%0,%1,%2,%3};"
        : "+f"(c[0]), "+f"(c[1]), "+f"(c[2]), "+f"(c[3])
        : "r"(a[0]), "r"(a[1]), "r"(a[2]), "r"(a[3]), "r"(b0), "r"(b1));
}
__device__ __forceinline__ void ldsm_x4(uint32_t& r0, uint32_t& r1, uint32_t& r2,
                                        uint32_t& r3, uint32_t addr) {
    asm volatile("ldmatrix.sync.aligned.m8n8.x4.shared.b16 {%0,%1,%2,%3},[%4];"
        : "=r"(r0), "=r"(r1), "=r"(r2), "=r"(r3) : "r"(addr));
}
__device__ __forceinline__ void ldsm_x4_t(uint32_t& r0, uint32_t& r1, uint32_t& r2,
                                          uint32_t& r3, uint32_t addr) {
    asm volatile("ldmatrix.sync.aligned.m8n8.x4.trans.shared.b16 {%0,%1,%2,%3},[%4];"
        : "=r"(r0), "=r"(r1), "=r"(r2), "=r"(r3) : "r"(addr));
}

// ---------------- fused prep (FIXED grid: 4096 x 6) ----------------
__global__ void prep_k(const float* __restrict__ fs, const float* __restrict__ fpe,
                       const float* __restrict__ os_, const float* __restrict__ ope,
                       float* __restrict__ out, __half* __restrict__ fsr,
                       __half* __restrict__ osr, __half* __restrict__ kvf,
                       __half* __restrict__ kvo) {
    const int i = blockIdx.x * 256 + threadIdx.x;
    const int seg = blockIdx.y;
    switch (seg) {
    case 0: ((float4*)(out + (size_t)MQ * Dm))[i] = ((const float4*)fs)[i]; break;
    case 1: ((float4*)(out + (size_t)MQ * Dm + (size_t)MKV * Dm))[i] = ((const float4*)os_)[i]; break;
    case 2: { float4 v = ((const float4*)fs)[i];
              ((uint2*)fsr)[i] = make_uint2(packh2(v.x, v.y), packh2(v.z, v.w)); break; }
    case 3: { float4 v = ((const float4*)os_)[i];
              ((uint2*)osr)[i] = make_uint2(packh2(v.x, v.y), packh2(v.z, v.w)); break; }
    case 4: { float4 a = ((const float4*)fs)[i], b = ((const float4*)fpe)[i];
              ((uint2*)kvf)[i] = make_uint2(packh2(a.x + b.x, a.y + b.y),
                                            packh2(a.z + b.z, a.w + b.w)); break; }
    default:{ float4 a = ((const float4*)os_)[i], b = ((const float4*)ope)[i];
              ((uint2*)kvo)[i] = make_uint2(packh2(a.x + b.x, a.y + b.y),
                                            packh2(a.z + b.z, a.w + b.w)); break; }
    }
}

// ---------------- fused weight transpose ----------------
struct TWSeg { const float* src; __half* dst; int K; int N; int tiles; };
struct TWTab { TWSeg s[10]; };
__global__ void tWall_k(TWTab tab) {
    __shared__ float t[32][33];
    int tI = blockIdx.x, j = 0;
#pragma unroll
    for (int q = 0; q < 9; q++) if (tI >= tab.s[j].tiles) { tI -= tab.s[j].tiles; j++; }
    const float* W = tab.s[j].src;
    __half* WT = tab.s[j].dst;
    const int K = tab.s[j].K, N = tab.s[j].N;
    const int ntx = N >> 5;
    const int n0 = (tI % ntx) * 32, k0 = (tI / ntx) * 32;
    const int tx = threadIdx.x, ty = threadIdx.y;
#pragma unroll
    for (int r = 0; r < 32; r += 8)
        t[ty + r][tx] = W[(size_t)(k0 + ty + r) * N + n0 + tx];
    __syncthreads();
#pragma unroll
    for (int r = 0; r < 32; r += 8)
        WT[(size_t)(n0 + ty + r) * K + k0 + tx] = __float2half_rn(t[tx][ty + r]);
}

// ---------------- layernorm (+ optional pe), half output ----------------
__global__ void ln_pe_k(const float* __restrict__ x, const float* __restrict__ g,
                        const float* __restrict__ b, const float* __restrict__ pe,
                        __half* __restrict__ out) {
    __shared__ float red[8];
    const int row = blockIdx.x, tid = threadIdx.x;
    const float* xr = x + (size_t)row * Dm;
    float4 xv = *(const float4*)&xr[tid * 4];
    float sum = xv.x + xv.y + xv.z + xv.w;
    float sq  = xv.x*xv.x + xv.y*xv.y + xv.z*xv.z + xv.w*xv.w;
#pragma unroll
    for (int off = 16; off > 0; off >>= 1) {
        sum += __shfl_xor_sync(0xffffffffu, sum, off);
        sq  += __shfl_xor_sync(0xffffffffu, sq,  off);
    }
    if ((tid & 31) == 0) { red[tid >> 5] = sum; red[4 + (tid >> 5)] = sq; }
    __syncthreads();
    sum = red[0] + red[1] + red[2] + red[3];
    sq  = red[4] + red[5] + red[6] + red[7];
    float mu   = sum * (1.0f / Dm);
    float var  = sq * (1.0f / Dm) - mu * mu;
    float rstd = rsqrtf(var + 1e-6f);
    float4 gv = *(const float4*)&g[tid * 4];
    float4 bv = *(const float4*)&b[tid * 4];
    float4 r;
    r.x = (xv.x - mu) * rstd * gv.x + bv.x;
    r.y = (xv.y - mu) * rstd * gv.y + bv.y;
    r.z = (xv.z - mu) * rstd * gv.z + bv.z;
    r.w = (xv.w - mu) * rstd * gv.w + bv.w;
    if (pe) {
        const float4 pv = *(const float4*)&pe[(size_t)row * Dm + tid * 4];
        r.x += pv.x; r.y += pv.y; r.z += pv.z; r.w += pv.w;
    }
    *(uint2*)&out[(size_t)row * Dm + tid * 4] = make_uint2(packh2(r.x, r.y), packh2(r.z, r.w));
}

// ---------------- fp16 GEMM, cp.async 3-stage, ldmatrix, templated BN ----------------
#define APITCH 40

template <int BN, bool RELU, bool RES, bool HOUT>
__global__ void __launch_bounds__(128) tgemm_k(
    const __half* __restrict__ A, const __half* __restrict__ WT,
    const float* __restrict__ bias, const float* __restrict__ res,
    void* __restrict__ C, int M, int N, int K, float scale)
{
    constexpr int NI   = BN / 16;
    constexpr int BP   = BN / 32;
    constexpr int GST  = (64 + BN) * APITCH * 2;
    extern __shared__ __half smh[];
    const int tid = threadIdx.x, lane = tid & 31, w = tid >> 5;
    const int wm = w >> 1, wn = w & 1;
    const int g = lane >> 2, qd = lane & 3;
    const int m0 = blockIdx.y * 64, n0 = blockIdx.x * BN;
    const uint32_t sbase = (uint32_t)__cvta_generic_to_shared(smh);

    // A fill: 2 adjacent 16B chunks per thread, halves [fca, fca+16)
    const int fra = tid >> 1, fca = (tid & 1) * 16;
    const __half* aSrc = A + (size_t)(m0 + fra) * K + fca;
    const uint32_t aDst = sbase + (fra * APITCH + fca) * 2;
    // B fill
    const int frb = (BP == 2) ? (tid >> 1) : tid;
    const int fcb = (BP == 2) ? ((tid & 1) * 16) : 0;
    const __half* bSrc = WT + (size_t)(n0 + frb) * K + fcb;
    const uint32_t bDst = sbase + ((64 + frb) * APITCH + fcb) * 2;

    const int L = lane;
    const uint32_t aOff = ((wm * 32 + ((L >> 3) & 1) * 8 + (L & 7)) * APITCH
                           + (L >> 4) * 8) * 2;
    const uint32_t bOff = ((64 + wn * (BN / 2) + (L >> 4) * 8 + (L & 7)) * APITCH
                           + ((L >> 3) & 1) * 8) * 2;

    const int KT = K >> 5;
#pragma unroll
    for (int pre = 0; pre < 2; pre++) {
        const __half* sa = aSrc + pre * 32;
        const __half* sb = bSrc + pre * 32;
        uint32_t da = aDst + pre * GST, db = bDst + pre * GST;
        cpa16(da, sa); cpa16(da + 16, sa + 8);
#pragma unroll
        for (int i = 0; i < ((BP == 2) ? 2 : 4); i++)
            cpa16(db + i * 16, sb + i * 8);
        cpa_commit();
    }

    float acc[2][NI][4];
#pragma unroll
    for (int mi = 0; mi < 2; mi++)
#pragma unroll
        for (int ni = 0; ni < NI; ni++)
#pragma unroll
            for (int e = 0; e < 4; e++) acc[mi][ni][e] = 0.f;

    for (int kt = 0; kt < KT; kt++) {
        cpa_wait<1>();
        __syncthreads();
        if (kt + 2 < KT) {
            int s2 = (kt + 2) % 3;
            const __half* sa = aSrc + (kt + 2) * 32;
            const __half* sb = bSrc + (kt + 2) * 32;
            uint32_t da = aDst + s2 * GST, db = bDst + s2 * GST;
            cpa16(da, sa); cpa16(da + 16, sa + 8);
#pragma unroll
            for (int i = 0; i < ((BP == 2) ? 2 : 4); i++)
                cpa16(db + i * 16, sb + i * 8);
        }
        cpa_commit();
        const uint32_t st = sbase + (kt % 3) * GST;
#pragma unroll
        for (int ks = 0; ks < 2; ks++) {
            uint32_t af[2][4], bf[NI][2];
#pragma unroll
            for (int mi = 0; mi < 2; mi++)
                ldsm_x4(af[mi][0], af[mi][1], af[mi][2], af[mi][3],
                        st + aOff + (mi * 16 * APITCH + ks * 16) * 2);
#pragma unroll
            for (int p = 0; p < BP; p++) {
                uint32_t r0, r1, r2, r3;
                ldsm_x4(r0, r1, r2, r3, st + bOff + (p * 16 * APITCH + ks * 16) * 2);
                bf[2*p][0] = r0; bf[2*p][1] = r1;
                bf[2*p+1][0] = r2; bf[2*p+1][1] = r3;
            }
#pragma unroll
            for (int mi = 0; mi < 2; mi++)
#pragma unroll
                for (int ni = 0; ni < NI; ni++)
                    mma_f16(acc[mi][ni], af[mi], bf[ni][0], bf[ni][1]);
        }
    }

#pragma unroll
    for (int mi = 0; mi < 2; mi++) {
        int mrow = m0 + wm * 32 + mi * 16 + g;
#pragma unroll
        for (int ni = 0; ni < NI; ni++) {
            int ncol = n0 + wn * (BN / 2) + ni * 8 + 2 * qd;
            float2 bv = *(const float2*)&bias[ncol];
#pragma unroll
            for (int hh = 0; hh < 2; hh++) {
                size_t m = (size_t)(mrow + hh * 8);
                float vx = acc[mi][ni][hh * 2 + 0] + bv.x;
                float vy = acc[mi][ni][hh * 2 + 1] + bv.y;
                if (RELU) { vx = fmaxf(vx, 0.f); vy = fmaxf(vy, 0.f); }
                vx *= scale; vy *= scale;
                if (HOUT) {
                    *(__half2*)((__half*)C + m * N + ncol) = __floats2half2_rn(vx, vy);
                } else {
                    if (RES) {
                        float2 rv = *(const float2*)&res[m * N + ncol];
                        vx += rv.x; vy += rv.y;
                    }
                    *(float2*)((float*)C + m * N + ncol) = make_float2(vx, vy);
                }
            }
        }
    }
}

// ---------------- fp16 flash attention, kv-split, double-buffered ----------------
#define FPITCH 72
#define QB  (64 * FPITCH * 2)
#define ATTN_SMEM (5 * QB)

__global__ void __launch_bounds__(64) fattn_k(
    const __half* __restrict__ Qm, const __half* __restrict__ Km,
    const __half* __restrict__ Vm, float* __restrict__ part, float* __restrict__ ml)
{
    extern __shared__ __half smf[];
    const uint32_t sbase = (uint32_t)__cvta_generic_to_shared(smf);
    const uint32_t sQ = sbase;

    const int tid = threadIdx.x;
    const int lane = tid & 31, w = tid >> 5;
    const int g = lane >> 2, qd = lane & 3;
    const int bb = blockIdx.z / SPLIT, sp = blockIdx.z % SPLIT;
    const int hh = blockIdx.y, qt = blockIdx.x;
    const size_t qrow0 = (size_t)bb * LQ + qt * 64;
    const int hoff = hh * DHd;
    const int mb = w * 32;
    const int L = lane;

    const int frr = tid >> 3, fcc = (tid & 7);
#pragma unroll
    for (int it = 0; it < 8; it++) {
        int r = frr + it * 8;
        cpa16(sQ + (r * FPITCH + fcc * 8) * 2, &Qm[(qrow0 + r) * Dm + hoff + fcc * 8]);
    }
    size_t kvb = (size_t)bb * LKV + (size_t)sp * TKV * 64;
#pragma unroll
    for (int it = 0; it < 8; it++) {
        int r = frr + it * 8;
        size_t gi = (kvb + r) * Dm + hoff + fcc * 8;
        cpa16(sQ + QB + (r * FPITCH + fcc * 8) * 2,     &Km[gi]);
        cpa16(sQ + 2 * QB + (r * FPITCH + fcc * 8) * 2, &Vm[gi]);
    }
    cpa_commit();
#pragma unroll
    for (int it = 0; it < 8; it++) {
        int r = frr + it * 8;
        size_t gi = (kvb + 64 + r) * Dm + hoff + fcc * 8;
        cpa16(sQ + 3 * QB + (r * FPITCH + fcc * 8) * 2, &Km[gi]);
        cpa16(sQ + 4 * QB + (r * FPITCH + fcc * 8) * 2, &Vm[gi]);
    }
    cpa_commit();

    const uint32_t qOff = ((mb + ((L >> 3) & 1) * 8 + (L & 7)) * FPITCH + (L >> 4) * 8) * 2;
    const uint32_t kOff = (((L >> 4) * 8 + (L & 7)) * FPITCH + ((L >> 3) & 1) * 8) * 2;
    const uint32_t vOff = ((L & 15) * FPITCH + (L >> 4) * 8) * 2;

    uint32_t aq[2][4][4];
    float o[2][8][4] = {};
    float mr[2][2] = {{-1e30f, -1e30f}, {-1e30f, -1e30f}};
    float lr[2][2] = {{0.f, 0.f}, {0.f, 0.f}};

    for (int t = 0; t < TKV; t++) {
        cpa_wait<1>();
        __syncthreads();
        if (t == 0) {
#pragma unroll
            for (int mi = 0; mi < 2; mi++)
#pragma unroll
                for (int ks = 0; ks < 4; ks++)
                    ldsm_x4(aq[mi][ks][0], aq[mi][ks][1], aq[mi][ks][2], aq[mi][ks][3],
                            sQ + qOff + (mi * 16 * FPITCH + ks * 16) * 2);
        }
        const uint32_t sK = sQ + QB + (t & 1) * 2 * QB;
        const uint32_t sV = sK + QB;

        float s[2][8][4] = {};
#pragma unroll
        for (int ks = 0; ks < 4; ks++) {
            uint32_t kb[8][2];
#pragma unroll
            for (int p = 0; p < 4; p++) {
                uint32_t r0, r1, r2, r3;
                ldsm_x4(r0, r1, r2, r3, sK + kOff + (p * 16 * FPITCH + ks * 16) * 2);
                kb[2*p][0] = r0; kb[2*p][1] = r1;
                kb[2*p+1][0] = r2; kb[2*p+1][1] = r3;
            }
#pragma unroll
            for (int mi = 0; mi < 2; mi++)
#pragma unroll
                for (int ni = 0; ni < 8; ni++)
                    mma_f16(s[mi][ni], aq[mi][ks], kb[ni][0], kb[ni][1]);
        }

        float es[2][2];
#pragma unroll
        for (int mi = 0; mi < 2; mi++) {
            float mx0 = -1e30f, mx1 = -1e30f;
#pragma unroll
            for (int ni = 0; ni < 8; ni++) {
                mx0 = fmaxf(mx0, fmaxf(s[mi][ni][0], s[mi][ni][1]));
                mx1 = fmaxf(mx1, fmaxf(s[mi][ni][2], s[mi][ni][3]));
            }
            mx0 = fmaxf(mx0, __shfl_xor_sync(~0u, mx0, 1));
            mx0 = fmaxf(mx0, __shfl_xor_sync(~0u, mx0, 2));
            mx1 = fmaxf(mx1, __shfl_xor_sync(~0u, mx1, 1));
            mx1 = fmaxf(mx1, __shfl_xor_sync(~0u, mx1, 2));
            float mn0 = fmaxf(mr[mi][0], mx0), mn1 = fmaxf(mr[mi][1], mx1);
            float sum0 = 0.f, sum1 = 0.f;
#pragma unroll
            for (int ni = 0; ni < 8; ni++) {
                s[mi][ni][0] = ex2(s[mi][ni][0] - mn0);
                s[mi][ni][1] = ex2(s[mi][ni][1] - mn0);
                s[mi][ni][2] = ex2(s[mi][ni][2] - mn1);
                s[mi][ni][3] = ex2(s[mi][ni][3] - mn1);
                sum0 += s[mi][ni][0] + s[mi][ni][1];
                sum1 += s[mi][ni][2] + s[mi][ni][3];
            }
            sum0 += __shfl_xor_sync(~0u, sum0, 1); sum0 += __shfl_xor_sync(~0u, sum0, 2);
            sum1 += __shfl_xor_sync(~0u, sum1, 1); sum1 += __shfl_xor_sync(~0u, sum1, 2);
            es[mi][0] = ex2(mr[mi][0] - mn0); es[mi][1] = ex2(mr[mi][1] - mn1);
            mr[mi][0] = mn0; mr[mi][1] = mn1;
            lr[mi][0] = lr[mi][0] * es[mi][0] + sum0;
            lr[mi][1] = lr[mi][1] * es[mi][1] + sum1;
#pragma unroll
            for (int ni = 0; ni < 8; ni++) {
                o[mi][ni][0] *= es[mi][0]; o[mi][ni][1] *= es[mi][0];
                o[mi][ni][2] *= es[mi][1]; o[mi][ni][3] *= es[mi][1];
            }
        }

#pragma unroll
        for (int ks = 0; ks < 4; ks++) {
            uint32_t vb[8][2];
#pragma unroll
            for (int j = 0; j < 4; j++) {
                uint32_t r0, r1, r2, r3;
                ldsm_x4_t(r0, r1, r2, r3, sV + vOff + (ks * 16 * FPITCH + j * 16) * 2);
                vb[2*j][0] = r0; vb[2*j][1] = r1;
                vb[2*j+1][0] = r2; vb[2*j+1][1] = r3;
            }
            uint32_t ap[2][4];
#pragma unroll
            for (int mi = 0; mi < 2; mi++) {
                ap[mi][0] = packh2(s[mi][2*ks][0],   s[mi][2*ks][1]);
                ap[mi][1] = packh2(s[mi][2*ks][2],   s[mi][2*ks][3]);
                ap[mi][2] = packh2(s[mi][2*ks+1][0], s[mi][2*ks+1][1]);
                ap[mi][3] = packh2(s[mi][2*ks+1][2], s[mi][2*ks+1][3]);
            }
#pragma unroll
            for (int mi = 0; mi < 2; mi++)
#pragma unroll
                for (int ni = 0; ni < 8; ni++)
                    mma_f16(o[mi][ni], ap[mi], vb[ni][0], vb[ni][1]);
        }

        __syncthreads();
        if (t + 2 < TKV) {
            size_t kv0 = kvb + (size_t)(t + 2) * 64;
            uint32_t dK = sQ + QB + (t & 1) * 2 * QB;
#pragma unroll
            for (int it = 0; it < 8; it++) {
                int r = frr + it * 8;
                size_t gi = (kv0 + r) * Dm + hoff + fcc * 8;
                cpa16(dK + (r * FPITCH + fcc * 8) * 2,      &Km[gi]);
                cpa16(dK + QB + (r * FPITCH + fcc * 8) * 2, &Vm[gi]);
            }
        }
        cpa_commit();
    }

#pragma unroll
    for (int mi = 0; mi < 2; mi++) {
        int rloc = mb + mi * 16 + g;
#pragma unroll
        for (int ni = 0; ni < 8; ni++) {
            int ncol = hoff + ni * 8 + 2 * qd;
            *(float2*)&part[((size_t)sp * MQ + qrow0 + rloc) * Dm + ncol] =
                make_float2(o[mi][ni][0], o[mi][ni][1]);
            *(float2*)&part[((size_t)sp * MQ + qrow0 + rloc + 8) * Dm + ncol] =
                make_float2(o[mi][ni][2], o[mi][ni][3]);
        }
        if (qd == 0) {
            size_t b0 = (((size_t)sp * MQ + qrow0 + rloc) * NH + hh) * 2;
            ml[b0] = mr[mi][0]; ml[b0 + 1] = lr[mi][0];
            size_t b1 = (((size_t)sp * MQ + qrow0 + rloc + 8) * NH + hh) * 2;
            ml[b1] = mr[mi][1]; ml[b1 + 1] = lr[mi][1];
        }
    }
}

// ---------------- split combine (half output) ----------------
__global__ void comb_k(const float* __restrict__ part, const float* __restrict__ ml,
                       __half* __restrict__ out) {
    int row = blockIdx.x, tid = threadIdx.x;
    int c = tid * 4, h = c >> 6;
    float m[SPLIT], l[SPLIT];
#pragma unroll
    for (int sp = 0; sp < SPLIT; sp++) {
        const float* p = &ml[(((size_t)sp * MQ + row) * NH + h) * 2];
        m[sp] = p[0]; l[sp] = p[1];
    }
    float M = m[0];
#pragma unroll
    for (int sp = 1; sp < SPLIT; sp++) M = fmaxf(M, m[sp]);
    float s[SPLIT], Lh = 0.f;
#pragma unroll
    for (int sp = 0; sp < SPLIT; sp++) { s[sp] = ex2(m[sp] - M); Lh += l[sp] * s[sp]; }
    float inv = 1.f / Lh;
    float4 a = make_float4(0.f, 0.f, 0.f, 0.f);
#pragma unroll
    for (int sp = 0; sp < SPLIT; sp++) {
        float4 v = *(const float4*)&part[((size_t)sp * MQ + row) * Dm + c];
        a.x += v.x * s[sp]; a.y += v.y * s[sp];
        a.z += v.z * s[sp]; a.w += v.w * s[sp];
    }
    *(uint2*)&out[(size_t)row * Dm + c] =
        make_uint2(packh2(a.x * inv, a.y * inv), packh2(a.z * inv, a.w * inv));
}

// ---------------- host ----------------
#define GSMEM64  (3 * (64 + 64)  * APITCH * 2)
#define GSMEM128 (3 * (64 + 128) * APITCH * 2)

extern "C" void kernel_launch(void* const* d_in, const int* in_sizes, int n_in,
                              void* d_out, int out_size) {
    const float* hs  = (const float*)d_in[0];
    const float* hpe = (const float*)d_in[1];
    const float* fs  = (const float*)d_in[2];
    const float* fpe = (const float*)d_in[3];
    const float* os_ = (const float*)d_in[4];
    const float* ope = (const float*)d_in[5];
    const float* f_Wq = (const float*)d_in[6],  *f_Wk = (const float*)d_in[7];
    const float* f_Wv = (const float*)d_in[8],  *f_Wo = (const float*)d_in[9];
    const float* f_bq = (const float*)d_in[10], *f_bk = (const float*)d_in[11];
    const float* f_bv = (const float*)d_in[12], *f_bo = (const float*)d_in[13];
    const float* f_g  = (const float*)d_in[14], *f_b  = (const float*)d_in[15];
    const float* o_Wq = (const float*)d_in[16], *o_Wk = (const float*)d_in[17];
    const float* o_Wv = (const float*)d_in[18], *o_Wo = (const float*)d_in[19];
    const float* o_bq = (const float*)d_in[20], *o_bk = (const float*)d_in[21];
    const float* o_bv = (const float*)d_in[22], *o_bo = (const float*)d_in[23];
    const float* o_g  = (const float*)d_in[24], *o_b  = (const float*)d_in[25];
    const float* W1 = (const float*)d_in[26], *b1 = (const float*)d_in[27];
    const float* W2 = (const float*)d_in[28], *b2 = (const float*)d_in[29];
    const float* n3g = (const float*)d_in[30], *n3b = (const float*)d_in[31];
    float* out = (float*)d_out;

    __half *ln, *kvf, *kvo, *fsr, *osr, *Qh, *Kh, *Vh, *at, *h1, *WT;
    float *x, *pt, *mlp;
    cudaGetSymbolAddress((void**)&ln,  hb_ln);
    cudaGetSymbolAddress((void**)&kvf, hb_kvf);
    cudaGetSymbolAddress((void**)&kvo, hb_kvo);
    cudaGetSymbolAddress((void**)&fsr, hb_fsr);
    cudaGetSymbolAddress((void**)&osr, hb_osr);
    cudaGetSymbolAddress((void**)&Qh,  hb_Q);
    cudaGetSymbolAddress((void**)&Kh,  hb_K);
    cudaGetSymbolAddress((void**)&Vh,  hb_V);
    cudaGetSymbolAddress((void**)&at,  hb_at);
    cudaGetSymbolAddress((void**)&h1,  hb_h1);
    cudaGetSymbolAddress((void**)&WT,  hb_WT);
    cudaGetSymbolAddress((void**)&x,   g_x);
    cudaGetSymbolAddress((void**)&pt,  g_part);
    cudaGetSymbolAddress((void**)&mlp, g_ml);

    cudaFuncSetAttribute(tgemm_k<64 ,false,false,true >, cudaFuncAttributeMaxDynamicSharedMemorySize, GSMEM64);
    cudaFuncSetAttribute(tgemm_k<64 ,false,true ,false>, cudaFuncAttributeMaxDynamicSharedMemorySize, GSMEM64);
    cudaFuncSetAttribute(tgemm_k<128,false,false,true >, cudaFuncAttributeMaxDynamicSharedMemorySize, GSMEM128);
    cudaFuncSetAttribute(tgemm_k<128,true ,false,true >, cudaFuncAttributeMaxDynamicSharedMemorySize, GSMEM128);
    cudaFuncSetAttribute(fattn_k, cudaFuncAttributeMaxDynamicSharedMemorySize, ATTN_SMEM);

    const float qscale = 0.125f * 1.4426950408889634f;
    dim3 g_q64(Dm / 64, MQ / 64);        // (8,32)  BN=64
    dim3 g_kv128(Dm / 128, MKV / 64);    // (4,128) BN=128
    dim3 g_ffn1(Ff / 128, MQ / 64);      // (16,32) BN=128
    dim3 g_attn(LQ / 64, NH, Bc * SPLIT);

    __half *rf_Wq = WT,               *rf_Wk = WT + 262144,
           *rf_Wv = WT + 2*262144,    *rf_Wo = WT + 3*262144,
           *ro_Wq = WT + 4*262144,    *ro_Wk = WT + 5*262144,
           *ro_Wv = WT + 6*262144,    *ro_Wo = WT + 7*262144,
           *rW1   = WT + 8*262144,    *rW2   = WT + 8*262144 + 1048576;

    // FIXED: each segment has MKV*Dm/4 = 1,048,576 float4s -> 4096 blocks x 256 thr
    prep_k<<<dim3(4096, 6), 256>>>(fs, fpe, os_, ope, out, fsr, osr, kvf, kvo);

    TWTab tab;
    tab.s[0] = {f_Wq, rf_Wq, Dm, Dm, 256};  tab.s[1] = {f_Wk, rf_Wk, Dm, Dm, 256};
    tab.s[2] = {f_Wv, rf_Wv, Dm, Dm, 256};  tab.s[3] = {f_Wo, rf_Wo, Dm, Dm, 256};
    tab.s[4] = {o_Wq, ro_Wq, Dm, Dm, 256};  tab.s[5] = {o_Wk, ro_Wk, Dm, Dm, 256};
    tab.s[6] = {o_Wv, ro_Wv, Dm, Dm, 256};  tab.s[7] = {o_Wo, ro_Wo, Dm, Dm, 256};
    tab.s[8] = {W1, rW1, Dm, Ff, 1024};     tab.s[9] = {W2, rW2, Ff, Dm, 1024};
    tWall_k<<<4096, dim3(32, 8)>>>(tab);

    // ---- frame cross-attention sublayer ----
    ln_pe_k<<<MQ, 128>>>(hs, f_g, f_b, hpe, ln);
    tgemm_k<64 ,false,false,true ><<<g_q64,   128, GSMEM64 >>>(ln,  rf_Wq, f_bq, nullptr, Qh, MQ,  Dm, Dm, qscale);
    tgemm_k<128,false,false,true ><<<g_kv128, 128, GSMEM128>>>(kvf, rf_Wk, f_bk, nullptr, Kh, MKV, Dm, Dm, 1.f);
    tgemm_k<128,false,false,true ><<<g_kv128, 128, GSMEM128>>>(fsr, rf_Wv, f_bv, nullptr, Vh, MKV, Dm, Dm, 1.f);
    fattn_k<<<g_attn, 64, ATTN_SMEM>>>(Qh, Kh, Vh, pt, mlp);
    comb_k<<<MQ, 128>>>(pt, mlp, at);
    tgemm_k<64 ,false,true ,false><<<g_q64, 128, GSMEM64>>>(at, rf_Wo, f_bo, hs, x, MQ, Dm, Dm, 1.f);

    // ---- object cross-attention sublayer ----
    ln_pe_k<<<MQ, 128>>>(x, o_g, o_b, hpe, ln);
    tgemm_k<64 ,false,false,true ><<<g_q64,   128, GSMEM64 >>>(ln,  ro_Wq, o_bq, nullptr, Qh, MQ,  Dm, Dm, qscale);
    tgemm_k<128,false,false,true ><<<g_kv128, 128, GSMEM128>>>(kvo, ro_Wk, o_bk, nullptr, Kh, MKV, Dm, Dm, 1.f);
    tgemm_k<128,false,false,true ><<<g_kv128, 128, GSMEM128>>>(osr, ro_Wv, o_bv, nullptr, Vh, MKV, Dm, Dm, 1.f);
    fattn_k<<<g_attn, 64, ATTN_SMEM>>>(Qh, Kh, Vh, pt, mlp);
    comb_k<<<MQ, 128>>>(pt, mlp, at);
    tgemm_k<64 ,false,true ,false><<<g_q64, 128, GSMEM64>>>(at, ro_Wo, o_bo, x, x, MQ, Dm, Dm, 1.f);

    // ---- FFN sublayer ----
    ln_pe_k<<<MQ, 128>>>(x, n3g, n3b, nullptr, ln);
    tgemm_k<128,true ,false,true ><<<g_ffn1, 128, GSMEM128>>>(ln, rW1, b1, nullptr, h1, MQ, Ff, Dm, 1.f);
    tgemm_k<64 ,false,true ,false><<<g_q64,  128, GSMEM64 >>>(h1, rW2, b2, x, out, MQ, Dm, Ff, 1.f);
}

// round 14
// speedup vs baseline: 5.5667x; 1.0978x over previous
#include <cuda_runtime.h>
#include <cuda_fp16.h>
#include <cstdint>

// ---------------- problem dims (fixed) ----------------
#define Bc   2
#define LQ   1024
#define LKV  4096
#define Dm   512
#define NH   8
#define DHd  64
#define Ff   2048
#define MQ   (Bc*LQ)    // 2048
#define MKV  (Bc*LKV)   // 8192
#define SPLIT 2
#define TKV  (LKV / 64 / SPLIT)   // 32

// ---------------- scratch (device globals) ----------------
__device__ __half hb_ln [MQ*Dm];
__device__ __half hb_kvf[MKV*Dm];
__device__ __half hb_kvo[MKV*Dm];
__device__ __half hb_fsr[MKV*Dm];
__device__ __half hb_osr[MKV*Dm];
__device__ __half hb_Q  [MQ*Dm];
__device__ __half hb_K  [MKV*Dm];
__device__ __half hb_V  [MKV*Dm];
__device__ __half hb_Ko [MKV*Dm];
__device__ __half hb_Vo [MKV*Dm];
__device__ __half hb_at [MQ*Dm];
__device__ __half hb_h1 [MQ*Ff];
__device__ __half hb_WT [8*262144 + 2*1048576];
__device__ float  g_x   [MQ*Dm];
__device__ float  g_part[SPLIT*MQ*Dm];
__device__ float  g_ml  [SPLIT*MQ*NH*2];

// ---------------- helpers ----------------
__device__ __forceinline__ uint32_t packh2(float a, float b) {
    __half2 h = __floats2half2_rn(a, b);
    return *(uint32_t*)&h;
}
__device__ __forceinline__ float ex2(float x) {
    float y; asm("ex2.approx.f32 %0, %1;" : "=f"(y) : "f"(x)); return y;
}
__device__ __forceinline__ void cpa16(uint32_t dst, const void* src) {
    asm volatile("cp.async.cg.shared.global [%0], [%1], 16;" :: "r"(dst), "l"(src));
}
__device__ __forceinline__ void cpa_commit() {
    asm volatile("cp.async.commit_group;" ::: "memory");
}
template <int N> __device__ __forceinline__ void cpa_wait() {
    asm volatile("cp.async.wait_group %0;" :: "n"(N) : "memory");
}
__device__ __forceinline__ void mma_f16(float c[4], const uint32_t a[4],
                                        uint32_t b0, uint32_t b1) {
    asm("mma.sync.aligned.m16n8k16.row.col.f32.f16.f16.f32 "
        "{%0,%1,%2,%3},{%4,%5,%6,%7},{%8,%9},{%0,%1,%2,%3};"
        : "+f"(c[0]), "+f"(c[1]), "+f"(c[2]), "+f"(c[3])
        : "r"(a[0]), "r"(a[1]), "r"(a[2]), "r"(a[3]), "r"(b0), "r"(b1));
}
__device__ __forceinline__ void ldsm_x4(uint32_t& r0, uint32_t& r1, uint32_t& r2,
                                        uint32_t& r3, uint32_t addr) {
    asm volatile("ldmatrix.sync.aligned.m8n8.x4.shared.b16 {%0,%1,%2,%3},[%4];"
        : "=r"(r0), "=r"(r1), "=r"(r2), "=r"(r3) : "r"(addr));
}
__device__ __forceinline__ void ldsm_x4_t(uint32_t& r0, uint32_t& r1, uint32_t& r2,
                                          uint32_t& r3, uint32_t addr) {
    asm volatile("ldmatrix.sync.aligned.m8n8.x4.trans.shared.b16 {%0,%1,%2,%3},[%4];"
        : "=r"(r0), "=r"(r1), "=r"(r2), "=r"(r3) : "r"(addr));
}

// ---------------- fused prep ----------------
__global__ void prep_k(const float* __restrict__ fs, const float* __restrict__ fpe,
                       const float* __restrict__ os_, const float* __restrict__ ope,
                       float* __restrict__ out, __half* __restrict__ fsr,
                       __half* __restrict__ osr, __half* __restrict__ kvf,
                       __half* __restrict__ kvo) {
    const int i = blockIdx.x * 256 + threadIdx.x;
    const int seg = blockIdx.y;
    switch (seg) {
    case 0: ((float4*)(out + (size_t)MQ * Dm))[i] = ((const float4*)fs)[i]; break;
    case 1: ((float4*)(out + (size_t)MQ * Dm + (size_t)MKV * Dm))[i] = ((const float4*)os_)[i]; break;
    case 2: { float4 v = ((const float4*)fs)[i];
              ((uint2*)fsr)[i] = make_uint2(packh2(v.x, v.y), packh2(v.z, v.w)); break; }
    case 3: { float4 v = ((const float4*)os_)[i];
              ((uint2*)osr)[i] = make_uint2(packh2(v.x, v.y), packh2(v.z, v.w)); break; }
    case 4: { float4 a = ((const float4*)fs)[i], b = ((const float4*)fpe)[i];
              ((uint2*)kvf)[i] = make_uint2(packh2(a.x + b.x, a.y + b.y),
                                            packh2(a.z + b.z, a.w + b.w)); break; }
    default:{ float4 a = ((const float4*)os_)[i], b = ((const float4*)ope)[i];
              ((uint2*)kvo)[i] = make_uint2(packh2(a.x + b.x, a.y + b.y),
                                            packh2(a.z + b.z, a.w + b.w)); break; }
    }
}

// ---------------- fused weight transpose ----------------
struct TWSeg { const float* src; __half* dst; int K; int N; int tiles; };
struct TWTab { TWSeg s[10]; };
__global__ void tWall_k(TWTab tab) {
    __shared__ float t[32][33];
    int tI = blockIdx.x, j = 0;
#pragma unroll
    for (int q = 0; q < 9; q++) if (tI >= tab.s[j].tiles) { tI -= tab.s[j].tiles; j++; }
    const float* W = tab.s[j].src;
    __half* WT = tab.s[j].dst;
    const int K = tab.s[j].K, N = tab.s[j].N;
    const int ntx = N >> 5;
    const int n0 = (tI % ntx) * 32, k0 = (tI / ntx) * 32;
    const int tx = threadIdx.x, ty = threadIdx.y;
#pragma unroll
    for (int r = 0; r < 32; r += 8)
        t[ty + r][tx] = W[(size_t)(k0 + ty + r) * N + n0 + tx];
    __syncthreads();
#pragma unroll
    for (int r = 0; r < 32; r += 8)
        WT[(size_t)(n0 + ty + r) * K + k0 + tx] = __float2half_rn(t[tx][ty + r]);
}

// ---------------- layernorm (+ optional pe), half output ----------------
__global__ void ln_pe_k(const float* __restrict__ x, const float* __restrict__ g,
                        const float* __restrict__ b, const float* __restrict__ pe,
                        __half* __restrict__ out) {
    __shared__ float red[8];
    const int row = blockIdx.x, tid = threadIdx.x;
    const float* xr = x + (size_t)row * Dm;
    float4 xv = *(const float4*)&xr[tid * 4];
    float sum = xv.x + xv.y + xv.z + xv.w;
    float sq  = xv.x*xv.x + xv.y*xv.y + xv.z*xv.z + xv.w*xv.w;
#pragma unroll
    for (int off = 16; off > 0; off >>= 1) {
        sum += __shfl_xor_sync(0xffffffffu, sum, off);
        sq  += __shfl_xor_sync(0xffffffffu, sq,  off);
    }
    if ((tid & 31) == 0) { red[tid >> 5] = sum; red[4 + (tid >> 5)] = sq; }
    __syncthreads();
    sum = red[0] + red[1] + red[2] + red[3];
    sq  = red[4] + red[5] + red[6] + red[7];
    float mu   = sum * (1.0f / Dm);
    float var  = sq * (1.0f / Dm) - mu * mu;
    float rstd = rsqrtf(var + 1e-6f);
    float4 gv = *(const float4*)&g[tid * 4];
    float4 bv = *(const float4*)&b[tid * 4];
    float4 r;
    r.x = (xv.x - mu) * rstd * gv.x + bv.x;
    r.y = (xv.y - mu) * rstd * gv.y + bv.y;
    r.z = (xv.z - mu) * rstd * gv.z + bv.z;
    r.w = (xv.w - mu) * rstd * gv.w + bv.w;
    if (pe) {
        const float4 pv = *(const float4*)&pe[(size_t)row * Dm + tid * 4];
        r.x += pv.x; r.y += pv.y; r.z += pv.z; r.w += pv.w;
    }
    *(uint2*)&out[(size_t)row * Dm + tid * 4] = make_uint2(packh2(r.x, r.y), packh2(r.z, r.w));
}

// ---------------- fp16 GEMM, cp.async 3-stage, ldmatrix, templated BN ----------------
#define APITCH 40

template <int BN, bool RELU, bool RES, bool HOUT>
__global__ void __launch_bounds__(128) tgemm_k(
    const __half* __restrict__ A, const __half* __restrict__ WT,
    const float* __restrict__ bias, const float* __restrict__ res,
    void* __restrict__ C, int M, int N, int K, float scale)
{
    constexpr int NI   = BN / 16;
    constexpr int BP   = BN / 32;
    constexpr int GST  = (64 + BN) * APITCH * 2;
    extern __shared__ __half smh[];
    const int tid = threadIdx.x, lane = tid & 31, w = tid >> 5;
    const int wm = w >> 1, wn = w & 1;
    const int g = lane >> 2, qd = lane & 3;
    const int m0 = blockIdx.y * 64, n0 = blockIdx.x * BN;
    const uint32_t sbase = (uint32_t)__cvta_generic_to_shared(smh);

    const int fra = tid >> 1, fca = (tid & 1) * 16;
    const __half* aSrc = A + (size_t)(m0 + fra) * K + fca;
    const uint32_t aDst = sbase + (fra * APITCH + fca) * 2;
    const int frb = (BP == 2) ? (tid >> 1) : tid;
    const int fcb = (BP == 2) ? ((tid & 1) * 16) : 0;
    const __half* bSrc = WT + (size_t)(n0 + frb) * K + fcb;
    const uint32_t bDst = sbase + ((64 + frb) * APITCH + fcb) * 2;

    const int L = lane;
    const uint32_t aOff = ((wm * 32 + ((L >> 3) & 1) * 8 + (L & 7)) * APITCH
                           + (L >> 4) * 8) * 2;
    const uint32_t bOff = ((64 + wn * (BN / 2) + (L >> 4) * 8 + (L & 7)) * APITCH
                           + ((L >> 3) & 1) * 8) * 2;

    const int KT = K >> 5;
#pragma unroll
    for (int pre = 0; pre < 2; pre++) {
        const __half* sa = aSrc + pre * 32;
        const __half* sb = bSrc + pre * 32;
        uint32_t da = aDst + pre * GST, db = bDst + pre * GST;
        cpa16(da, sa); cpa16(da + 16, sa + 8);
#pragma unroll
        for (int i = 0; i < ((BP == 2) ? 2 : 4); i++)
            cpa16(db + i * 16, sb + i * 8);
        cpa_commit();
    }

    float acc[2][NI][4];
#pragma unroll
    for (int mi = 0; mi < 2; mi++)
#pragma unroll
        for (int ni = 0; ni < NI; ni++)
#pragma unroll
            for (int e = 0; e < 4; e++) acc[mi][ni][e] = 0.f;

    for (int kt = 0; kt < KT; kt++) {
        cpa_wait<1>();
        __syncthreads();
        if (kt + 2 < KT) {
            int s2 = (kt + 2) % 3;
            const __half* sa = aSrc + (kt + 2) * 32;
            const __half* sb = bSrc + (kt + 2) * 32;
            uint32_t da = aDst + s2 * GST, db = bDst + s2 * GST;
            cpa16(da, sa); cpa16(da + 16, sa + 8);
#pragma unroll
            for (int i = 0; i < ((BP == 2) ? 2 : 4); i++)
                cpa16(db + i * 16, sb + i * 8);
        }
        cpa_commit();
        const uint32_t st = sbase + (kt % 3) * GST;
#pragma unroll
        for (int ks = 0; ks < 2; ks++) {
            uint32_t af[2][4], bf[NI][2];
#pragma unroll
            for (int mi = 0; mi < 2; mi++)
                ldsm_x4(af[mi][0], af[mi][1], af[mi][2], af[mi][3],
                        st + aOff + (mi * 16 * APITCH + ks * 16) * 2);
#pragma unroll
            for (int p = 0; p < BP; p++) {
                uint32_t r0, r1, r2, r3;
                ldsm_x4(r0, r1, r2, r3, st + bOff + (p * 16 * APITCH + ks * 16) * 2);
                bf[2*p][0] = r0; bf[2*p][1] = r1;
                bf[2*p+1][0] = r2; bf[2*p+1][1] = r3;
            }
#pragma unroll
            for (int mi = 0; mi < 2; mi++)
#pragma unroll
                for (int ni = 0; ni < NI; ni++)
                    mma_f16(acc[mi][ni], af[mi], bf[ni][0], bf[ni][1]);
        }
    }

#pragma unroll
    for (int mi = 0; mi < 2; mi++) {
        int mrow = m0 + wm * 32 + mi * 16 + g;
#pragma unroll
        for (int ni = 0; ni < NI; ni++) {
            int ncol = n0 + wn * (BN / 2) + ni * 8 + 2 * qd;
            float2 bv = *(const float2*)&bias[ncol];
#pragma unroll
            for (int hh = 0; hh < 2; hh++) {
                size_t m = (size_t)(mrow + hh * 8);
                float vx = acc[mi][ni][hh * 2 + 0] + bv.x;
                float vy = acc[mi][ni][hh * 2 + 1] + bv.y;
                if (RELU) { vx = fmaxf(vx, 0.f); vy = fmaxf(vy, 0.f); }
                vx *= scale; vy *= scale;
                if (HOUT) {
                    *(__half2*)((__half*)C + m * N + ncol) = __floats2half2_rn(vx, vy);
                } else {
                    if (RES) {
                        float2 rv = *(const float2*)&res[m * N + ncol];
                        vx += rv.x; vy += rv.y;
                    }
                    *(float2*)((float*)C + m * N + ncol) = make_float2(vx, vy);
                }
            }
        }
    }
}

// ---------------- fp16 flash attention, kv-split, double-buffered ----------------
#define FPITCH 72
#define QB  (64 * FPITCH * 2)
#define ATTN_SMEM (5 * QB)

__global__ void __launch_bounds__(64) fattn_k(
    const __half* __restrict__ Qm, const __half* __restrict__ Km,
    const __half* __restrict__ Vm, float* __restrict__ part, float* __restrict__ ml)
{
    extern __shared__ __half smf[];
    const uint32_t sbase = (uint32_t)__cvta_generic_to_shared(smf);
    const uint32_t sQ = sbase;

    const int tid = threadIdx.x;
    const int lane = tid & 31, w = tid >> 5;
    const int g = lane >> 2, qd = lane & 3;
    const int bb = blockIdx.z / SPLIT, sp = blockIdx.z % SPLIT;
    const int hh = blockIdx.y, qt = blockIdx.x;
    const size_t qrow0 = (size_t)bb * LQ + qt * 64;
    const int hoff = hh * DHd;
    const int mb = w * 32;
    const int L = lane;

    const int frr = tid >> 3, fcc = (tid & 7);
#pragma unroll
    for (int it = 0; it < 8; it++) {
        int r = frr + it * 8;
        cpa16(sQ + (r * FPITCH + fcc * 8) * 2, &Qm[(qrow0 + r) * Dm + hoff + fcc * 8]);
    }
    size_t kvb = (size_t)bb * LKV + (size_t)sp * TKV * 64;
#pragma unroll
    for (int it = 0; it < 8; it++) {
        int r = frr + it * 8;
        size_t gi = (kvb + r) * Dm + hoff + fcc * 8;
        cpa16(sQ + QB + (r * FPITCH + fcc * 8) * 2,     &Km[gi]);
        cpa16(sQ + 2 * QB + (r * FPITCH + fcc * 8) * 2, &Vm[gi]);
    }
    cpa_commit();
#pragma unroll
    for (int it = 0; it < 8; it++) {
        int r = frr + it * 8;
        size_t gi = (kvb + 64 + r) * Dm + hoff + fcc * 8;
        cpa16(sQ + 3 * QB + (r * FPITCH + fcc * 8) * 2, &Km[gi]);
        cpa16(sQ + 4 * QB + (r * FPITCH + fcc * 8) * 2, &Vm[gi]);
    }
    cpa_commit();

    const uint32_t qOff = ((mb + ((L >> 3) & 1) * 8 + (L & 7)) * FPITCH + (L >> 4) * 8) * 2;
    const uint32_t kOff = (((L >> 4) * 8 + (L & 7)) * FPITCH + ((L >> 3) & 1) * 8) * 2;
    const uint32_t vOff = ((L & 15) * FPITCH + (L >> 4) * 8) * 2;

    uint32_t aq[2][4][4];
    float o[2][8][4] = {};
    float mr[2][2] = {{-1e30f, -1e30f}, {-1e30f, -1e30f}};
    float lr[2][2] = {{0.f, 0.f}, {0.f, 0.f}};

    for (int t = 0; t < TKV; t++) {
        cpa_wait<1>();
        __syncthreads();
        if (t == 0) {
#pragma unroll
            for (int mi = 0; mi < 2; mi++)
#pragma unroll
                for (int ks = 0; ks < 4; ks++)
                    ldsm_x4(aq[mi][ks][0], aq[mi][ks][1], aq[mi][ks][2], aq[mi][ks][3],
                            sQ + qOff + (mi * 16 * FPITCH + ks * 16) * 2);
        }
        const uint32_t sK = sQ + QB + (t & 1) * 2 * QB;
        const uint32_t sV = sK + QB;

        float s[2][8][4] = {};
#pragma unroll
        for (int ks = 0; ks < 4; ks++) {
            uint32_t kb[8][2];
#pragma unroll
            for (int p = 0; p < 4; p++) {
                uint32_t r0, r1, r2, r3;
                ldsm_x4(r0, r1, r2, r3, sK + kOff + (p * 16 * FPITCH + ks * 16) * 2);
                kb[2*p][0] = r0; kb[2*p][1] = r1;
                kb[2*p+1][0] = r2; kb[2*p+1][1] = r3;
            }
#pragma unroll
            for (int mi = 0; mi < 2; mi++)
#pragma unroll
                for (int ni = 0; ni < 8; ni++)
                    mma_f16(s[mi][ni], aq[mi][ks], kb[ni][0], kb[ni][1]);
        }

        float es[2][2];
#pragma unroll
        for (int mi = 0; mi < 2; mi++) {
            float mx0 = -1e30f, mx1 = -1e30f;
#pragma unroll
            for (int ni = 0; ni < 8; ni++) {
                mx0 = fmaxf(mx0, fmaxf(s[mi][ni][0], s[mi][ni][1]));
                mx1 = fmaxf(mx1, fmaxf(s[mi][ni][2], s[mi][ni][3]));
            }
            mx0 = fmaxf(mx0, __shfl_xor_sync(~0u, mx0, 1));
            mx0 = fmaxf(mx0, __shfl_xor_sync(~0u, mx0, 2));
            mx1 = fmaxf(mx1, __shfl_xor_sync(~0u, mx1, 1));
            mx1 = fmaxf(mx1, __shfl_xor_sync(~0u, mx1, 2));
            float mn0 = fmaxf(mr[mi][0], mx0), mn1 = fmaxf(mr[mi][1], mx1);
            float sum0 = 0.f, sum1 = 0.f;
#pragma unroll
            for (int ni = 0; ni < 8; ni++) {
                s[mi][ni][0] = ex2(s[mi][ni][0] - mn0);
                s[mi][ni][1] = ex2(s[mi][ni][1] - mn0);
                s[mi][ni][2] = ex2(s[mi][ni][2] - mn1);
                s[mi][ni][3] = ex2(s[mi][ni][3] - mn1);
                sum0 += s[mi][ni][0] + s[mi][ni][1];
                sum1 += s[mi][ni][2] + s[mi][ni][3];
            }
            sum0 += __shfl_xor_sync(~0u, sum0, 1); sum0 += __shfl_xor_sync(~0u, sum0, 2);
            sum1 += __shfl_xor_sync(~0u, sum1, 1); sum1 += __shfl_xor_sync(~0u, sum1, 2);
            es[mi][0] = ex2(mr[mi][0] - mn0); es[mi][1] = ex2(mr[mi][1] - mn1);
            mr[mi][0] = mn0; mr[mi][1] = mn1;
            lr[mi][0] = lr[mi][0] * es[mi][0] + sum0;
            lr[mi][1] = lr[mi][1] * es[mi][1] + sum1;
#pragma unroll
            for (int ni = 0; ni < 8; ni++) {
                o[mi][ni][0] *= es[mi][0]; o[mi][ni][1] *= es[mi][0];
                o[mi][ni][2] *= es[mi][1]; o[mi][ni][3] *= es[mi][1];
            }
        }

#pragma unroll
        for (int ks = 0; ks < 4; ks++) {
            uint32_t vb[8][2];
#pragma unroll
            for (int j = 0; j < 4; j++) {
                uint32_t r0, r1, r2, r3;
                ldsm_x4_t(r0, r1, r2, r3, sV + vOff + (ks * 16 * FPITCH + j * 16) * 2);
                vb[2*j][0] = r0; vb[2*j][1] = r1;
                vb[2*j+1][0] = r2; vb[2*j+1][1] = r3;
            }
            uint32_t ap[2][4];
#pragma unroll
            for (int mi = 0; mi < 2; mi++) {
                ap[mi][0] = packh2(s[mi][2*ks][0],   s[mi][2*ks][1]);
                ap[mi][1] = packh2(s[mi][2*ks][2],   s[mi][2*ks][3]);
                ap[mi][2] = packh2(s[mi][2*ks+1][0], s[mi][2*ks+1][1]);
                ap[mi][3] = packh2(s[mi][2*ks+1][2], s[mi][2*ks+1][3]);
            }
#pragma unroll
            for (int mi = 0; mi < 2; mi++)
#pragma unroll
                for (int ni = 0; ni < 8; ni++)
                    mma_f16(o[mi][ni], ap[mi], vb[ni][0], vb[ni][1]);
        }

        __syncthreads();
        if (t + 2 < TKV) {
            size_t kv0 = kvb + (size_t)(t + 2) * 64;
            uint32_t dK = sQ + QB + (t & 1) * 2 * QB;
#pragma unroll
            for (int it = 0; it < 8; it++) {
                int r = frr + it * 8;
                size_t gi = (kv0 + r) * Dm + hoff + fcc * 8;
                cpa16(dK + (r * FPITCH + fcc * 8) * 2,      &Km[gi]);
                cpa16(dK + QB + (r * FPITCH + fcc * 8) * 2, &Vm[gi]);
            }
        }
        cpa_commit();
    }

#pragma unroll
    for (int mi = 0; mi < 2; mi++) {
        int rloc = mb + mi * 16 + g;
#pragma unroll
        for (int ni = 0; ni < 8; ni++) {
            int ncol = hoff + ni * 8 + 2 * qd;
            *(float2*)&part[((size_t)sp * MQ + qrow0 + rloc) * Dm + ncol] =
                make_float2(o[mi][ni][0], o[mi][ni][1]);
            *(float2*)&part[((size_t)sp * MQ + qrow0 + rloc + 8) * Dm + ncol] =
                make_float2(o[mi][ni][2], o[mi][ni][3]);
        }
        if (qd == 0) {
            size_t b0 = (((size_t)sp * MQ + qrow0 + rloc) * NH + hh) * 2;
            ml[b0] = mr[mi][0]; ml[b0 + 1] = lr[mi][0];
            size_t b1 = (((size_t)sp * MQ + qrow0 + rloc + 8) * NH + hh) * 2;
            ml[b1] = mr[mi][1]; ml[b1 + 1] = lr[mi][1];
        }
    }
}

// ---------------- split combine (half output) ----------------
__global__ void comb_k(const float* __restrict__ part, const float* __restrict__ ml,
                       __half* __restrict__ out) {
    int row = blockIdx.x, tid = threadIdx.x;
    int c = tid * 4, h = c >> 6;
    float m[SPLIT], l[SPLIT];
#pragma unroll
    for (int sp = 0; sp < SPLIT; sp++) {
        const float* p = &ml[(((size_t)sp * MQ + row) * NH + h) * 2];
        m[sp] = p[0]; l[sp] = p[1];
    }
    float M = m[0];
#pragma unroll
    for (int sp = 1; sp < SPLIT; sp++) M = fmaxf(M, m[sp]);
    float s[SPLIT], Lh = 0.f;
#pragma unroll
    for (int sp = 0; sp < SPLIT; sp++) { s[sp] = ex2(m[sp] - M); Lh += l[sp] * s[sp]; }
    float inv = 1.f / Lh;
    float4 a = make_float4(0.f, 0.f, 0.f, 0.f);
#pragma unroll
    for (int sp = 0; sp < SPLIT; sp++) {
        float4 v = *(const float4*)&part[((size_t)sp * MQ + row) * Dm + c];
        a.x += v.x * s[sp]; a.y += v.y * s[sp];
        a.z += v.z * s[sp]; a.w += v.w * s[sp];
    }
    *(uint2*)&out[(size_t)row * Dm + c] =
        make_uint2(packh2(a.x * inv, a.y * inv), packh2(a.z * inv, a.w * inv));
}

// ---------------- host ----------------
#define GSMEM64  (3 * (64 + 64)  * APITCH * 2)
#define GSMEM128 (3 * (64 + 128) * APITCH * 2)

// Streams/events created ONCE on the first (correctness, pre-capture-baseline)
// call and reused. Side streams are forked from the origin stream via evRoot
// BEFORE any side-stream launch, so all side-stream work is capture-reachable.
static cudaStream_t g_sA = nullptr, g_sB = nullptr;
static cudaEvent_t g_evRoot, g_evW, g_evP, g_evKf, g_evVf, g_evKo, g_evVo;

extern "C" void kernel_launch(void* const* d_in, const int* in_sizes, int n_in,
                              void* d_out, int out_size) {
    const float* hs  = (const float*)d_in[0];
    const float* hpe = (const float*)d_in[1];
    const float* fs  = (const float*)d_in[2];
    const float* fpe = (const float*)d_in[3];
    const float* os_ = (const float*)d_in[4];
    const float* ope = (const float*)d_in[5];
    const float* f_Wq = (const float*)d_in[6],  *f_Wk = (const float*)d_in[7];
    const float* f_Wv = (const float*)d_in[8],  *f_Wo = (const float*)d_in[9];
    const float* f_bq = (const float*)d_in[10], *f_bk = (const float*)d_in[11];
    const float* f_bv = (const float*)d_in[12], *f_bo = (const float*)d_in[13];
    const float* f_g  = (const float*)d_in[14], *f_b  = (const float*)d_in[15];
    const float* o_Wq = (const float*)d_in[16], *o_Wk = (const float*)d_in[17];
    const float* o_Wv = (const float*)d_in[18], *o_Wo = (const float*)d_in[19];
    const float* o_bq = (const float*)d_in[20], *o_bk = (const float*)d_in[21];
    const float* o_bv = (const float*)d_in[22], *o_bo = (const float*)d_in[23];
    const float* o_g  = (const float*)d_in[24], *o_b  = (const float*)d_in[25];
    const float* W1 = (const float*)d_in[26], *b1 = (const float*)d_in[27];
    const float* W2 = (const float*)d_in[28], *b2 = (const float*)d_in[29];
    const float* n3g = (const float*)d_in[30], *n3b = (const float*)d_in[31];
    float* out = (float*)d_out;

    __half *ln, *kvf, *kvo, *fsr, *osr, *Qh, *Kh, *Vh, *Koh, *Voh, *at, *h1, *WT;
    float *x, *pt, *mlp;
    cudaGetSymbolAddress((void**)&ln,  hb_ln);
    cudaGetSymbolAddress((void**)&kvf, hb_kvf);
    cudaGetSymbolAddress((void**)&kvo, hb_kvo);
    cudaGetSymbolAddress((void**)&fsr, hb_fsr);
    cudaGetSymbolAddress((void**)&osr, hb_osr);
    cudaGetSymbolAddress((void**)&Qh,  hb_Q);
    cudaGetSymbolAddress((void**)&Kh,  hb_K);
    cudaGetSymbolAddress((void**)&Vh,  hb_V);
    cudaGetSymbolAddress((void**)&Koh, hb_Ko);
    cudaGetSymbolAddress((void**)&Voh, hb_Vo);
    cudaGetSymbolAddress((void**)&at,  hb_at);
    cudaGetSymbolAddress((void**)&h1,  hb_h1);
    cudaGetSymbolAddress((void**)&WT,  hb_WT);
    cudaGetSymbolAddress((void**)&x,   g_x);
    cudaGetSymbolAddress((void**)&pt,  g_part);
    cudaGetSymbolAddress((void**)&mlp, g_ml);

    cudaFuncSetAttribute(tgemm_k<64 ,false,false,true >, cudaFuncAttributeMaxDynamicSharedMemorySize, GSMEM64);
    cudaFuncSetAttribute(tgemm_k<64 ,false,true ,false>, cudaFuncAttributeMaxDynamicSharedMemorySize, GSMEM64);
    cudaFuncSetAttribute(tgemm_k<128,false,false,true >, cudaFuncAttributeMaxDynamicSharedMemorySize, GSMEM128);
    cudaFuncSetAttribute(tgemm_k<128,true ,false,true >, cudaFuncAttributeMaxDynamicSharedMemorySize, GSMEM128);
    cudaFuncSetAttribute(fattn_k, cudaFuncAttributeMaxDynamicSharedMemorySize, ATTN_SMEM);

    if (!g_sA) {
        cudaStreamCreateWithFlags(&g_sA, cudaStreamNonBlocking);
        cudaStreamCreateWithFlags(&g_sB, cudaStreamNonBlocking);
        cudaEventCreateWithFlags(&g_evRoot, cudaEventDisableTiming);
        cudaEventCreateWithFlags(&g_evW,  cudaEventDisableTiming);
        cudaEventCreateWithFlags(&g_evP,  cudaEventDisableTiming);
        cudaEventCreateWithFlags(&g_evKf, cudaEventDisableTiming);
        cudaEventCreateWithFlags(&g_evVf, cudaEventDisableTiming);
        cudaEventCreateWithFlags(&g_evKo, cudaEventDisableTiming);
        cudaEventCreateWithFlags(&g_evVo, cudaEventDisableTiming);
    }
    cudaStream_t sA = g_sA, sB = g_sB;

    const float qscale = 0.125f * 1.4426950408889634f;
    dim3 g_q64(Dm / 64, MQ / 64);        // (8,32)  BN=64
    dim3 g_kv128(Dm / 128, MKV / 64);    // (4,128) BN=128
    dim3 g_ffn1(Ff / 128, MQ / 64);      // (16,32) BN=128
    dim3 g_attn(LQ / 64, NH, Bc * SPLIT);

    __half *rf_Wq = WT,               *rf_Wk = WT + 262144,
           *rf_Wv = WT + 2*262144,    *rf_Wo = WT + 3*262144,
           *ro_Wq = WT + 4*262144,    *ro_Wk = WT + 5*262144,
           *ro_Wv = WT + 6*262144,    *ro_Wo = WT + 7*262144,
           *rW1   = WT + 8*262144,    *rW2   = WT + 8*262144 + 1048576;

    TWTab tab;
    tab.s[0] = {f_Wq, rf_Wq, Dm, Dm, 256};  tab.s[1] = {f_Wk, rf_Wk, Dm, Dm, 256};
    tab.s[2] = {f_Wv, rf_Wv, Dm, Dm, 256};  tab.s[3] = {f_Wo, rf_Wo, Dm, Dm, 256};
    tab.s[4] = {o_Wq, ro_Wq, Dm, Dm, 256};  tab.s[5] = {o_Wk, ro_Wk, Dm, Dm, 256};
    tab.s[6] = {o_Wv, ro_Wv, Dm, Dm, 256};  tab.s[7] = {o_Wo, ro_Wo, Dm, Dm, 256};
    tab.s[8] = {W1, rW1, Dm, Ff, 1024};     tab.s[9] = {W2, rW2, Ff, Dm, 1024};

    // ---- fork side streams from the capture-origin stream FIRST ----
    cudaEventRecord(g_evRoot, 0);
    cudaStreamWaitEvent(sA, g_evRoot, 0);
    cudaStreamWaitEvent(sB, g_evRoot, 0);

    // ---- main stream: weights (needed by Q-proj first) ----
    tWall_k<<<4096, dim3(32, 8)>>>(tab);
    cudaEventRecord(g_evW, 0);

    // ---- side stream A: prep, then K projections ----
    prep_k<<<dim3(4096, 6), 256, 0, sA>>>(fs, fpe, os_, ope, out, fsr, osr, kvf, kvo);
    cudaEventRecord(g_evP, sA);
    cudaStreamWaitEvent(sA, g_evW, 0);
    tgemm_k<128,false,false,true ><<<g_kv128, 128, GSMEM128, sA>>>(kvf, rf_Wk, f_bk, nullptr, Kh,  MKV, Dm, Dm, 1.f);
    cudaEventRecord(g_evKf, sA);
    tgemm_k<128,false,false,true ><<<g_kv128, 128, GSMEM128, sA>>>(kvo, ro_Wk, o_bk, nullptr, Koh, MKV, Dm, Dm, 1.f);
    cudaEventRecord(g_evKo, sA);

    // ---- side stream B: V projections ----
    cudaStreamWaitEvent(sB, g_evP, 0);
    cudaStreamWaitEvent(sB, g_evW, 0);
    tgemm_k<128,false,false,true ><<<g_kv128, 128, GSMEM128, sB>>>(fsr, rf_Wv, f_bv, nullptr, Vh,  MKV, Dm, Dm, 1.f);
    cudaEventRecord(g_evVf, sB);
    tgemm_k<128,false,false,true ><<<g_kv128, 128, GSMEM128, sB>>>(osr, ro_Wv, o_bv, nullptr, Voh, MKV, Dm, Dm, 1.f);
    cudaEventRecord(g_evVo, sB);

    // ---- main stream: critical chain ----
    ln_pe_k<<<MQ, 128>>>(hs, f_g, f_b, hpe, ln);
    tgemm_k<64 ,false,false,true ><<<g_q64, 128, GSMEM64>>>(ln, rf_Wq, f_bq, nullptr, Qh, MQ, Dm, Dm, qscale);
    cudaStreamWaitEvent(0, g_evKf, 0);
    cudaStreamWaitEvent(0, g_evVf, 0);
    fattn_k<<<g_attn, 64, ATTN_SMEM>>>(Qh, Kh, Vh, pt, mlp);
    comb_k<<<MQ, 128>>>(pt, mlp, at);
    tgemm_k<64 ,false,true ,false><<<g_q64, 128, GSMEM64>>>(at, rf_Wo, f_bo, hs, x, MQ, Dm, Dm, 1.f);

    ln_pe_k<<<MQ, 128>>>(x, o_g, o_b, hpe, ln);
    tgemm_k<64 ,false,false,true ><<<g_q64, 128, GSMEM64>>>(ln, ro_Wq, o_bq, nullptr, Qh, MQ, Dm, Dm, qscale);
    cudaStreamWaitEvent(0, g_evKo, 0);
    cudaStreamWaitEvent(0, g_evVo, 0);
    fattn_k<<<g_attn, 64, ATTN_SMEM>>>(Qh, Koh, Voh, pt, mlp);
    comb_k<<<MQ, 128>>>(pt, mlp, at);
    tgemm_k<64 ,false,true ,false><<<g_q64, 128, GSMEM64>>>(at, ro_Wo, o_bo, x, x, MQ, Dm, Dm, 1.f);

    ln_pe_k<<<MQ, 128>>>(x, n3g, n3b, nullptr, ln);
    tgemm_k<128,true ,false,true ><<<g_ffn1, 128, GSMEM128>>>(ln, rW1, b1, nullptr, h1, MQ, Ff, Dm, 1.f);
    tgemm_k<64 ,false,true ,false><<<g_q64,  128, GSMEM64 >>>(h1, rW2, b2, x, out, MQ, Dm, Ff, 1.f);
}